// round 14
// baseline (speedup 1.0000x reference)
#include <cuda_runtime.h>
#include <cuda_bf16.h>
#include <cstdint>

#define T    4
#define HH   64
#define HE   16
#define HD   128
#define EPB  32
#define ROWS 128
#define STRIDE 132
#define NPRE 32
#define NPB  32
#define MAXN 20000
#define EPSF 1e-8f
#define BROW 272          // bf16 operand row stride in bytes (136 bf16)

typedef unsigned long long u64;
typedef unsigned int u32;

// ---------------- device globals ----------------
__device__ float g_mi[MAXN * T * HD];          // [N, T, HD]
__device__ float g_agg[MAXN * 3 * T];
__device__ float g_cnt[MAXN];
__device__ float g_p1[(size_t)MAXN * T * HD];
__device__ float g_p2[(size_t)MAXN * T * HD];
__device__ float g_zerobias[HD];
// plain [n][k] bf16 hi/lo images of W2^T and CW1^T
__device__ __nv_bfloat16 g_w2hi[HD * HD], g_w2lo[HD * HD];
__device__ __nv_bfloat16 g_c1hi[HD * HD], g_c1lo[HD * HD];

__device__ __forceinline__ float silu_f(float v) {
    return v * __fdividef(1.0f, 1.0f + __expf(-v));
}

#define FMA2(d, a, b) asm("fma.rn.f32x2 %0, %1, %2, %0;" : "+l"(d) : "l"(a), "l"(b))
__device__ __forceinline__ u64 packab(float a, float b) {
    u64 r; asm("mov.b64 %0, {%1, %2};" : "=l"(r) : "f"(a), "f"(b)); return r;
}
__device__ __forceinline__ u64 pack2(float v) { return packab(v, v); }
__device__ __forceinline__ void unpack2(u64 v, float& lo, float& hi) {
    asm("mov.b64 {%0, %1}, %2;" : "=f"(lo), "=f"(hi) : "l"(v));
}
__device__ __forceinline__ u32 smem_u32(const void* p) {
    u32 a;
    asm("{ .reg .u64 t; cvta.to.shared.u64 t, %1; cvt.u32.u64 %0, t; }"
        : "=r"(a) : "l"(p));
    return a;
}
// bf16 pair hi/lo split
__device__ __forceinline__ void split2(float a, float b, u32& h, u32& l) {
    __nv_bfloat162 hp, lp;
    hp.x = __float2bfloat16(a); hp.y = __float2bfloat16(b);
    lp.x = __float2bfloat16(a - __bfloat162float(hp.x));
    lp.y = __float2bfloat16(b - __bfloat162float(hp.y));
    h = *reinterpret_cast<u32*>(&hp);
    l = *reinterpret_cast<u32*>(&lp);
}

#define LDMX4(r0, r1, r2, r3, addr) \
    asm volatile("ldmatrix.sync.aligned.m8n8.x4.shared.b16 {%0,%1,%2,%3}, [%4];" \
        : "=r"(r0), "=r"(r1), "=r"(r2), "=r"(r3) : "r"(addr))

#define MMA16816(d, a0, a1, a2, a3, b0, b1) \
    asm volatile("mma.sync.aligned.m16n8k16.row.col.f32.bf16.bf16.f32 " \
        "{%0,%1,%2,%3}, {%4,%5,%6,%7}, {%8,%9}, {%0,%1,%2,%3};" \
        : "+f"((d)[0]), "+f"((d)[1]), "+f"((d)[2]), "+f"((d)[3]) \
        : "r"(a0), "r"(a1), "r"(a2), "r"(a3), "r"(b0), "r"(b1))

#define REDV2(p, v0, v1) \
    asm volatile("red.global.add.v2.f32 [%0], {%1,%2};" \
                 :: "l"(p), "f"(v0), "f"(v1) : "memory")

// ---------------- small kernels ----------------
__global__ void zero_kernel(int n) {
    int stride = gridDim.x * blockDim.x;
    int base = blockIdx.x * blockDim.x + threadIdx.x;
    for (int i = base; i < n * HD * T; i += stride) g_mi[i] = 0.0f;
    for (int i = base; i < n * 3 * T;  i += stride) g_agg[i] = 0.0f;
    for (int i = base; i < n;          i += stride) g_cnt[i] = 0.0f;
}

// plain [n][k] bf16 hi/lo weight images (B^T: img[n*128+k] = W[k][n])
__global__ void wimg_kernel(const float* __restrict__ w2, const float* __restrict__ cw1) {
    int idx = blockIdx.x * 256 + threadIdx.x;   // 16384
    int n = idx >> 7, k = idx & 127;
    float v2 = w2[k * HD + n];
    __nv_bfloat16 h2 = __float2bfloat16(v2);
    g_w2hi[idx] = h2;
    g_w2lo[idx] = __float2bfloat16(v2 - __bfloat162float(h2));
    float v3 = cw1[k * HD + n];
    __nv_bfloat16 h3 = __float2bfloat16(v3);
    g_c1hi[idx] = h3;
    g_c1lo[idx] = __float2bfloat16(v3 - __bfloat162float(h3));
}

// ---------------- FFMA2 GEMM tile (pre/node kernels) ----------------
template<int NCHUNK, int KLIM, bool ACT>
__device__ __forceinline__ void gemm_phase(
    const float* __restrict__ sA, float* __restrict__ sW,
    const float* __restrict__ gW, const float* __restrict__ gB,
    int tid, int tx, int ty, float (&out)[8][8])
{
    u64 acc[8][4];
    {
        float4 bA = *(const float4*)(gB + 4 * tx);
        float4 bB = *(const float4*)(gB + 64 + 4 * tx);
        u64 i0 = packab(bA.x, bA.y), i1 = packab(bA.z, bA.w);
        u64 i2 = packab(bB.x, bB.y), i3 = packab(bB.z, bB.w);
#pragma unroll
        for (int r = 0; r < 8; r++) {
            acc[r][0] = i0; acc[r][1] = i1; acc[r][2] = i2; acc[r][3] = i3;
        }
    }
    float4 pre[4];
#pragma unroll
    for (int i = 0; i < 4; i++) {
        int off = i * 1024 + tid * 4;
        int kg = off >> 7;
        pre[i] = (kg < KLIM) ? *(const float4*)(gW + kg * HD + (off & 127))
                             : make_float4(0.f, 0.f, 0.f, 0.f);
    }
#pragma unroll 1
    for (int kc = 0; kc < NCHUNK; kc++) {
        __syncthreads();
#pragma unroll
        for (int i = 0; i < 4; i++)
            *(float4*)(sW + i * 1024 + tid * 4) = pre[i];
        __syncthreads();
        if (kc + 1 < NCHUNK) {
#pragma unroll
            for (int i = 0; i < 4; i++) {
                int off = i * 1024 + tid * 4;
                int kg = (kc + 1) * 32 + (off >> 7);
                pre[i] = (kg < KLIM) ? *(const float4*)(gW + kg * HD + (off & 127))
                                     : make_float4(0.f, 0.f, 0.f, 0.f);
            }
        }
        const float* ap = sA + (kc * 32) * STRIDE + ty * 8;
#pragma unroll 8
        for (int kk = 0; kk < 32; kk++) {
            float4 a0 = *(const float4*)(ap);
            float4 a1 = *(const float4*)(ap + 4);
            ap += STRIDE;
            ulonglong2 bA = *(const ulonglong2*)(sW + kk * HD + 4 * tx);
            ulonglong2 bB = *(const ulonglong2*)(sW + kk * HD + 64 + 4 * tx);
            float av[8] = {a0.x, a0.y, a0.z, a0.w, a1.x, a1.y, a1.z, a1.w};
#pragma unroll
            for (int r = 0; r < 8; r++) {
                u64 ar = pack2(av[r]);
                FMA2(acc[r][0], ar, bA.x);
                FMA2(acc[r][1], ar, bA.y);
                FMA2(acc[r][2], ar, bB.x);
                FMA2(acc[r][3], ar, bB.y);
            }
        }
    }
#pragma unroll
    for (int r = 0; r < 8; r++)
#pragma unroll
        for (int cp = 0; cp < 4; cp++) {
            float lo, hi; unpack2(acc[r][cp], lo, hi);
            out[r][cp * 2]     = ACT ? silu_f(lo) : lo;
            out[r][cp * 2 + 1] = ACT ? silu_f(hi) : hi;
        }
}

// ---------------- P1/P2 precompute ----------------
__global__ __launch_bounds__(256, 2) void pre_kernel(
    const float* __restrict__ h, const float* __restrict__ w1, int N)
{
    extern __shared__ float sm[];
    float* s_h = sm;
    float* s_w = sm + HH * STRIDE;
    const int tid = threadIdx.x, tx = tid & 15, ty = tid >> 4;
    const int n0 = blockIdx.x * NPRE;
#pragma unroll
    for (int it = 0; it < 8; it++) {
        int idx = it * 256 + tid;
        int k = idx & 63, nl = idx >> 6;
        int node = n0 + nl; if (node >= N) node = N - 1;
        float4 v = *(const float4*)(h + ((size_t)node * HH + k) * T);
        *(float4*)(s_h + k * STRIDE + nl * 4) = v;
    }
    float o[8][8];
    gemm_phase<2, HH, false>(s_h, s_w, w1, g_zerobias, tid, tx, ty, o);
#pragma unroll
    for (int r = 0; r < 8; r++) {
        int row = ty * 8 + r;
        int node = n0 + (row >> 2), t = row & 3;
        if (node < N) {
            float* p = g_p1 + ((size_t)node * T + t) * HD;
            *(float4*)(p + 4 * tx)      = make_float4(o[r][0], o[r][1], o[r][2], o[r][3]);
            *(float4*)(p + 64 + 4 * tx) = make_float4(o[r][4], o[r][5], o[r][6], o[r][7]);
        }
    }
    gemm_phase<2, HH, false>(s_h, s_w, w1 + HH * HD, g_zerobias, tid, tx, ty, o);
#pragma unroll
    for (int r = 0; r < 8; r++) {
        int row = ty * 8 + r;
        int node = n0 + (row >> 2), t = row & 3;
        if (node < N) {
            float* p = g_p2 + ((size_t)node * T + t) * HD;
            *(float4*)(p + 4 * tx)      = make_float4(o[r][0], o[r][1], o[r][2], o[r][3]);
            *(float4*)(p + 64 + 4 * tx) = make_float4(o[r][4], o[r][5], o[r][6], o[r][7]);
        }
    }
}

// ---------------- edge kernel: FFMA2 layer-1 + HMMA split-bf16 GEMMs ----------------
__global__ __launch_bounds__(256, 1) void edge_kernel(
    const float* __restrict__ x,
    const int* __restrict__ ei, const float* __restrict__ ea,
    const float* __restrict__ w1, const float* __restrict__ b1,
    const float* __restrict__ b2, const float* __restrict__ cb1,
    const float* __restrict__ cw2, const float* __restrict__ cb2,
    int E)
{
    extern __shared__ __align__(16) char smc[];
    char* sAhi = smc;                 // 128 x 272B = 34816
    char* sAlo = smc + 34816;
    char* sBhi = smc + 69632;
    char* sBlo = smc + 104448;
    float* s_ea   = (float*)(smc + 139264);   // 16 x STRIDE floats
    float* s_w1   = (float*)(smc + 147712);   // 17 x 128 floats
    float* s_bias = (float*)(smc + 156416);   // b2|cb1|cw2

    __shared__ int   s_rown[EPB], s_coln[EPB];
    __shared__ float s_xij[EPB][3][T];
    __shared__ float s_n2[ROWS];

    const int tid = threadIdx.x, tx = tid & 15, ty = tid >> 4;
    const int wid = tid >> 5, t5 = tid & 31;
    const int e0 = blockIdx.x * EPB;

    const u32 sAhi_b = smem_u32(sAhi), sAlo_b = smem_u32(sAlo);
    const u32 sBhi_b = smem_u32(sBhi), sBlo_b = smem_u32(sBlo);

    if (tid < EPB) {
        int eg = e0 + tid; if (eg >= E) eg = E - 1;
        s_rown[tid] = ei[eg];
        s_coln[tid] = ei[E + eg];
    }

    // stage Bhi/Blo = W2 images (row-major 128x256B -> 272B stride)
    {
        int row = tid >> 1, half = tid & 1;
        const float4* sh = (const float4*)((const char*)g_w2hi + row * 256 + half * 128);
        const float4* sl = (const float4*)((const char*)g_w2lo + row * 256 + half * 128);
        float4* dh = (float4*)(sBhi + row * BROW + half * 128);
        float4* dl = (float4*)(sBlo + row * BROW + half * 128);
#pragma unroll
        for (int q = 0; q < 8; q++) { dh[q] = sh[q]; dl[q] = sl[q]; }
    }
    // stage W1 rows 129..144 + row 128
    for (int i = tid; i < 17 * 32; i += 256) {
        int k = i >> 5, cg = i & 31;
        int srcrow = (k == 16) ? 128 : (129 + k);
        *(float4*)(s_w1 + k * HD + cg * 4) = *(const float4*)(w1 + srcrow * HD + cg * 4);
    }
    if (tid < 128) {
        s_bias[tid]       = b2[tid];
        s_bias[128 + tid] = cb1[tid];
        s_bias[256 + tid] = cw2[tid];
    }
    __syncthreads();

    // edge_attr gather
#pragma unroll
    for (int it = 0; it < 2; it++) {
        int idx = it * 256 + tid;
        int k = idx & 15, e = idx >> 4;
        int eg = e0 + e; if (eg >= E) eg = E - 1;
        float4 v = *(const float4*)(ea + ((size_t)eg * HE + k) * T);
        *(float4*)(s_ea + k * STRIDE + e * 4) = v;
    }
    // x_ij, n2
    if (tid < ROWS) {
        int e = tid >> 2, t = tid & 3;
        int rn = s_rown[e], cn = s_coln[e];
        float n2 = 0.f;
#pragma unroll
        for (int d = 0; d < 3; d++) {
            float v = x[((size_t)rn * 3 + d) * T + t] - x[((size_t)cn * 3 + d) * T + t];
            s_xij[e][d][t] = v;
            n2 += v * v;
        }
        s_n2[tid] = n2;
    }
    __syncthreads();

    // ---- layer 1 (FFMA2) ----
    float o1[8][8];
    {
        u64 acc[8][4];
        float4 bA = *(const float4*)(b1 + 4 * tx);
        float4 bB = *(const float4*)(b1 + 64 + 4 * tx);
        float4 wA = *(const float4*)(s_w1 + 16 * HD + 4 * tx);
        float4 wB = *(const float4*)(s_w1 + 16 * HD + 64 + 4 * tx);
#pragma unroll
        for (int r = 0; r < 8; r++) {
            int row = ty * 8 + r;
            int e = row >> 2, t = row & 3;
            const float* p1 = g_p1 + ((size_t)s_rown[e] * T + t) * HD;
            const float* p2 = g_p2 + ((size_t)s_coln[e] * T + t) * HD;
            float4 a1 = *(const float4*)(p1 + 4 * tx);
            float4 c1 = *(const float4*)(p1 + 64 + 4 * tx);
            float4 a2 = *(const float4*)(p2 + 4 * tx);
            float4 c2 = *(const float4*)(p2 + 64 + 4 * tx);
            float n2r = s_n2[row];
            acc[r][0] = packab(bA.x + a1.x + a2.x + n2r * wA.x,
                               bA.y + a1.y + a2.y + n2r * wA.y);
            acc[r][1] = packab(bA.z + a1.z + a2.z + n2r * wA.z,
                               bA.w + a1.w + a2.w + n2r * wA.w);
            acc[r][2] = packab(bB.x + c1.x + c2.x + n2r * wB.x,
                               bB.y + c1.y + c2.y + n2r * wB.y);
            acc[r][3] = packab(bB.z + c1.z + c2.z + n2r * wB.z,
                               bB.w + c1.w + c2.w + n2r * wB.w);
        }
        const float* ap = s_ea + ty * 8;
#pragma unroll
        for (int k = 0; k < HE; k++) {
            float4 a0 = *(const float4*)(ap);
            float4 a1 = *(const float4*)(ap + 4);
            ap += STRIDE;
            ulonglong2 wp0 = *(const ulonglong2*)(s_w1 + k * HD + 4 * tx);
            ulonglong2 wp1 = *(const ulonglong2*)(s_w1 + k * HD + 64 + 4 * tx);
            float av[8] = {a0.x, a0.y, a0.z, a0.w, a1.x, a1.y, a1.z, a1.w};
#pragma unroll
            for (int r = 0; r < 8; r++) {
                u64 ar = pack2(av[r]);
                FMA2(acc[r][0], ar, wp0.x);
                FMA2(acc[r][1], ar, wp0.y);
                FMA2(acc[r][2], ar, wp1.x);
                FMA2(acc[r][3], ar, wp1.y);
            }
        }
#pragma unroll
        for (int r = 0; r < 8; r++)
#pragma unroll
            for (int cp = 0; cp < 4; cp++) {
                float lo, hi; unpack2(acc[r][cp], lo, hi);
                o1[r][2 * cp]     = silu_f(lo);
                o1[r][2 * cp + 1] = silu_f(hi);
            }
    }

    // ---- stage o1 -> sAhi/sAlo (bf16, 272B rows) ----
#pragma unroll
    for (int r = 0; r < 8; r++) {
        int row = ty * 8 + r;
#pragma unroll
        for (int g2 = 0; g2 < 2; g2++) {
            int cb = g2 ? (64 + 4 * tx) : (4 * tx);
            u32 h01, l01, h23, l23;
            split2(o1[r][4 * g2 + 0], o1[r][4 * g2 + 1], h01, l01);
            split2(o1[r][4 * g2 + 2], o1[r][4 * g2 + 3], h23, l23);
            *(uint2*)(sAhi + row * BROW + cb * 2) = make_uint2(h01, h23);
            *(uint2*)(sAlo + row * BROW + cb * 2) = make_uint2(l01, l23);
        }
    }
    __syncthreads();

    // ldmatrix per-thread offsets
    const u32 aoff = (u32)((wid * 16 + (t5 & 15)) * BROW + ((t5 & 16) ? 16 : 0));
    const u32 boff = (u32)(((t5 & 7) + ((t5 >> 4) << 3)) * BROW + ((t5 & 8) << 1));

    float d[16][4];
#pragma unroll
    for (int n = 0; n < 16; n++)
#pragma unroll
        for (int q = 0; q < 4; q++) d[n][q] = 0.f;

    // ---- GEMM1: (Ahi+Alo)@Bhi ----
#pragma unroll 1
    for (int ks = 0; ks < 8; ks++) {
        u32 ah[4], al[4];
        LDMX4(ah[0], ah[1], ah[2], ah[3], sAhi_b + aoff + ks * 32);
        LDMX4(al[0], al[1], al[2], al[3], sAlo_b + aoff + ks * 32);
#pragma unroll
        for (int j = 0; j < 8; j++) {
            u32 b0, b1, b2r, b3;
            LDMX4(b0, b1, b2r, b3, sBhi_b + boff + j * (16 * BROW) + ks * 32);
            MMA16816(d[2 * j],     ah[0], ah[1], ah[2], ah[3], b0, b1);
            MMA16816(d[2 * j + 1], ah[0], ah[1], ah[2], ah[3], b2r, b3);
            MMA16816(d[2 * j],     al[0], al[1], al[2], al[3], b0, b1);
            MMA16816(d[2 * j + 1], al[0], al[1], al[2], al[3], b2r, b3);
        }
    }
    // ---- GEMM1: Ahi@Blo ----
#pragma unroll 1
    for (int ks = 0; ks < 8; ks++) {
        u32 ah[4];
        LDMX4(ah[0], ah[1], ah[2], ah[3], sAhi_b + aoff + ks * 32);
#pragma unroll
        for (int j = 0; j < 8; j++) {
            u32 b0, b1, b2r, b3;
            LDMX4(b0, b1, b2r, b3, sBlo_b + boff + j * (16 * BROW) + ks * 32);
            MMA16816(d[2 * j],     ah[0], ah[1], ah[2], ah[3], b0, b1);
            MMA16816(d[2 * j + 1], ah[0], ah[1], ah[2], ah[3], b2r, b3);
        }
    }

    // ---- readback GEMM1: +b2, silu, scatter m_i, build GEMM2 A-frags ----
    const int g = t5 >> 2, tg = t5 & 3;
    const int rowA = wid * 16 + g, rowB = rowA + 8;
    const int eA = rowA >> 2, tA = rowA & 3;
    const int eB = rowB >> 2, tB = rowB & 3;
    const bool okA = (e0 + eA) < E, okB = (e0 + eB) < E;
    float* mA = g_mi + ((size_t)s_rown[eA] * T + tA) * HD;
    float* mB = g_mi + ((size_t)s_rown[eB] * T + tB) * HD;

    u32 a2h[8][4], a2l[8][4];
#pragma unroll
    for (int n = 0; n < 16; n++) {
        int c = 8 * n + 2 * tg;
        float v0 = silu_f(d[n][0] + s_bias[c]);
        float v1 = silu_f(d[n][1] + s_bias[c + 1]);
        float v2 = silu_f(d[n][2] + s_bias[c]);
        float v3 = silu_f(d[n][3] + s_bias[c + 1]);
        if (okA) REDV2(mA + c, v0, v1);
        if (okB) REDV2(mB + c, v2, v3);
        int ks = n >> 1, p = n & 1;
        split2(v0, v1, a2h[ks][2 * p],     a2l[ks][2 * p]);
        split2(v2, v3, a2h[ks][2 * p + 1], a2l[ks][2 * p + 1]);
    }
    __syncthreads();

    // restage B = CW1 images
    {
        int row = tid >> 1, half = tid & 1;
        const float4* sh = (const float4*)((const char*)g_c1hi + row * 256 + half * 128);
        const float4* sl = (const float4*)((const char*)g_c1lo + row * 256 + half * 128);
        float4* dh = (float4*)(sBhi + row * BROW + half * 128);
        float4* dl = (float4*)(sBlo + row * BROW + half * 128);
#pragma unroll
        for (int q = 0; q < 8; q++) { dh[q] = sh[q]; dl[q] = sl[q]; }
    }
    __syncthreads();

#pragma unroll
    for (int n = 0; n < 16; n++)
#pragma unroll
        for (int q = 0; q < 4; q++) d[n][q] = 0.f;

    // ---- GEMM2: (A2hi+A2lo)@Bhi ----
#pragma unroll 1
    for (int ks = 0; ks < 8; ks++) {
#pragma unroll
        for (int j = 0; j < 8; j++) {
            u32 b0, b1, b2r, b3;
            LDMX4(b0, b1, b2r, b3, sBhi_b + boff + j * (16 * BROW) + ks * 32);
            MMA16816(d[2 * j],     a2h[ks][0], a2h[ks][1], a2h[ks][2], a2h[ks][3], b0, b1);
            MMA16816(d[2 * j + 1], a2h[ks][0], a2h[ks][1], a2h[ks][2], a2h[ks][3], b2r, b3);
            MMA16816(d[2 * j],     a2l[ks][0], a2l[ks][1], a2l[ks][2], a2l[ks][3], b0, b1);
            MMA16816(d[2 * j + 1], a2l[ks][0], a2l[ks][1], a2l[ks][2], a2l[ks][3], b2r, b3);
        }
    }
    // ---- GEMM2: A2hi@Blo ----
#pragma unroll 1
    for (int ks = 0; ks < 8; ks++) {
#pragma unroll
        for (int j = 0; j < 8; j++) {
            u32 b0, b1, b2r, b3;
            LDMX4(b0, b1, b2r, b3, sBlo_b + boff + j * (16 * BROW) + ks * 32);
            MMA16816(d[2 * j],     a2h[ks][0], a2h[ks][1], a2h[ks][2], a2h[ks][3], b0, b1);
            MMA16816(d[2 * j + 1], a2h[ks][0], a2h[ks][1], a2h[ks][2], a2h[ks][3], b2r, b3);
        }
    }

    // ---- readback GEMM2: silu, dot cw2, quad-reduce, coord epilogue ----
    {
        float pA = 0.f, pB = 0.f;
#pragma unroll
        for (int n = 0; n < 16; n++) {
            int c = 8 * n + 2 * tg;
            pA += silu_f(d[n][0] + s_bias[128 + c])     * s_bias[256 + c];
            pA += silu_f(d[n][1] + s_bias[128 + c + 1]) * s_bias[256 + c + 1];
            pB += silu_f(d[n][2] + s_bias[128 + c])     * s_bias[256 + c];
            pB += silu_f(d[n][3] + s_bias[128 + c + 1]) * s_bias[256 + c + 1];
        }
        pA += __shfl_xor_sync(0xffffffffu, pA, 1);
        pA += __shfl_xor_sync(0xffffffffu, pA, 2);
        pB += __shfl_xor_sync(0xffffffffu, pB, 1);
        pB += __shfl_xor_sync(0xffffffffu, pB, 2);
        if (tg == 0) {
            float cb2v = cb2[0];
#pragma unroll
            for (int half = 0; half < 2; half++) {
                int row = half ? rowB : rowA;
                float p = half ? pB : pA;
                int e = row >> 2, t = row & 3;
                if (e0 + e < E) {
                    float cval = (p + cb2v) *
                        __fdividef(1.0f, sqrtf(s_n2[row] + EPSF) + 1.0f);
                    int node = s_rown[e];
#pragma unroll
                    for (int dd = 0; dd < 3; dd++)
                        atomicAdd(&g_agg[((size_t)node * 3 + dd) * T + t],
                                  cval * s_xij[e][dd][t]);
                    if (t == 0) atomicAdd(&g_cnt[node], 1.0f);
                }
            }
        }
    }
}

// ---------------- node kernel ([N,T,HD] g_mi gather) ----------------
__global__ __launch_bounds__(256, 2) void node_kernel(
    const float* __restrict__ x, const float* __restrict__ h,
    const float* __restrict__ nw1, const float* __restrict__ nb1,
    const float* __restrict__ nw2, const float* __restrict__ nb2,
    float* __restrict__ out_x, float* __restrict__ out_h, int N)
{
    extern __shared__ float sm[];
    float* s_buf = sm;
    float* s_w   = sm + HD * STRIDE;

    const int tid = threadIdx.x, tx = tid & 15, ty = tid >> 4;
    const int n0 = blockIdx.x * NPB;

#pragma unroll
    for (int it = 0; it < 2; it++) {
        int idx = it * 256 + tid;
        if (idx < NPB * 12) {
            int n = n0 + idx / 12;
            if (n < N) {
                int rem = idx % 12, d = rem >> 2, t = rem & 3;
                float cv = fmaxf(g_cnt[n], 1.0f);
                int off = (n * 3 + d) * T + t;
                out_x[off] = x[off] + g_agg[off] * __fdividef(1.0f, cv);
            }
        }
    }

    // stage A part 1: ch 0..63 = h; ch 64..127 = m_i k 0..63
#pragma unroll
    for (int it = 0; it < 8; it++) {
        int idx = it * 256 + tid;
        int k = idx & 63, nl = idx >> 6;
        int node = n0 + nl; if (node >= N) node = N - 1;
        float4 v = *(const float4*)(h + ((size_t)node * HH + k) * T);
        *(float4*)(s_buf + k * STRIDE + nl * 4) = v;
    }
#pragma unroll
    for (int it = 0; it < 8; it++) {
        int idx = it * 256 + tid;
        int kq = idx & 15, t = (idx >> 4) & 3, nl = idx >> 6;
        int node = n0 + nl; if (node >= N) node = N - 1;
        float4 v = *(const float4*)(g_mi + ((size_t)node * T + t) * HD + kq * 4);
        s_buf[(HH + kq * 4 + 0) * STRIDE + nl * 4 + t] = v.x;
        s_buf[(HH + kq * 4 + 1) * STRIDE + nl * 4 + t] = v.y;
        s_buf[(HH + kq * 4 + 2) * STRIDE + nl * 4 + t] = v.z;
        s_buf[(HH + kq * 4 + 3) * STRIDE + nl * 4 + t] = v.w;
    }

    u64 acc[8][4];
    {
        float4 bA = *(const float4*)(nb1 + 4 * tx);
        float4 bB = *(const float4*)(nb1 + 64 + 4 * tx);
        u64 i0 = packab(bA.x, bA.y), i1 = packab(bA.z, bA.w);
        u64 i2 = packab(bB.x, bB.y), i3 = packab(bB.z, bB.w);
#pragma unroll
        for (int r = 0; r < 8; r++) {
            acc[r][0] = i0; acc[r][1] = i1; acc[r][2] = i2; acc[r][3] = i3;
        }
    }
    float4 pre[4];
#pragma unroll
    for (int i = 0; i < 4; i++) {
        int off = i * 1024 + tid * 4;
        pre[i] = *(const float4*)(nw1 + (off >> 7) * HD + (off & 127));
    }
#pragma unroll 1
    for (int kc = 0; kc < 4; kc++) {
        __syncthreads();
#pragma unroll
        for (int i = 0; i < 4; i++)
            *(float4*)(s_w + i * 1024 + tid * 4) = pre[i];
        __syncthreads();
        {
            int kbase = (kc + 1) * 32;
            if (kbase < 192) {
#pragma unroll
                for (int i = 0; i < 4; i++) {
                    int off = i * 1024 + tid * 4;
                    pre[i] = *(const float4*)(nw1 + (kbase + (off >> 7)) * HD + (off & 127));
                }
            }
        }
        const float* ap = s_buf + (kc * 32) * STRIDE + ty * 8;
#pragma unroll 8
        for (int kk = 0; kk < 32; kk++) {
            float4 a0 = *(const float4*)(ap);
            float4 a1 = *(const float4*)(ap + 4);
            ap += STRIDE;
            ulonglong2 bA = *(const ulonglong2*)(s_w + kk * HD + 4 * tx);
            ulonglong2 bB = *(const ulonglong2*)(s_w + kk * HD + 64 + 4 * tx);
            float av[8] = {a0.x, a0.y, a0.z, a0.w, a1.x, a1.y, a1.z, a1.w};
#pragma unroll
            for (int r = 0; r < 8; r++) {
                u64 ar = pack2(av[r]);
                FMA2(acc[r][0], ar, bA.x);
                FMA2(acc[r][1], ar, bA.y);
                FMA2(acc[r][2], ar, bB.x);
                FMA2(acc[r][3], ar, bB.y);
            }
        }
    }
    __syncthreads();

    // stage A part 2: m_i k 64..127
#pragma unroll
    for (int it = 0; it < 8; it++) {
        int idx = it * 256 + tid;
        int kq = idx & 15, t = (idx >> 4) & 3, nl = idx >> 6;
        int node = n0 + nl; if (node >= N) node = N - 1;
        float4 v = *(const float4*)(g_mi + ((size_t)node * T + t) * HD + 64 + kq * 4);
        s_buf[(kq * 4 + 0) * STRIDE + nl * 4 + t] = v.x;
        s_buf[(kq * 4 + 1) * STRIDE + nl * 4 + t] = v.y;
        s_buf[(kq * 4 + 2) * STRIDE + nl * 4 + t] = v.z;
        s_buf[(kq * 4 + 3) * STRIDE + nl * 4 + t] = v.w;
    }
#pragma unroll 1
    for (int kc = 0; kc < 2; kc++) {
        __syncthreads();
#pragma unroll
        for (int i = 0; i < 4; i++)
            *(float4*)(s_w + i * 1024 + tid * 4) = pre[i];
        __syncthreads();
        if (kc == 0) {
#pragma unroll
            for (int i = 0; i < 4; i++) {
                int off = i * 1024 + tid * 4;
                pre[i] = *(const float4*)(nw1 + (160 + (off >> 7)) * HD + (off & 127));
            }
        }
        const float* ap = s_buf + (kc * 32) * STRIDE + ty * 8;
#pragma unroll 8
        for (int kk = 0; kk < 32; kk++) {
            float4 a0 = *(const float4*)(ap);
            float4 a1 = *(const float4*)(ap + 4);
            ap += STRIDE;
            ulonglong2 bA = *(const ulonglong2*)(s_w + kk * HD + 4 * tx);
            ulonglong2 bB = *(const ulonglong2*)(s_w + kk * HD + 64 + 4 * tx);
            float av[8] = {a0.x, a0.y, a0.z, a0.w, a1.x, a1.y, a1.z, a1.w};
#pragma unroll
            for (int r = 0; r < 8; r++) {
                u64 ar = pack2(av[r]);
                FMA2(acc[r][0], ar, bA.x);
                FMA2(acc[r][1], ar, bA.y);
                FMA2(acc[r][2], ar, bB.x);
                FMA2(acc[r][3], ar, bB.y);
            }
        }
    }

    float o1[8][8];
#pragma unroll
    for (int r = 0; r < 8; r++)
#pragma unroll
        for (int cp = 0; cp < 4; cp++) {
            float lo, hi; unpack2(acc[r][cp], lo, hi);
            o1[r][2 * cp]     = silu_f(lo);
            o1[r][2 * cp + 1] = silu_f(hi);
        }
    __syncthreads();
#pragma unroll
    for (int c = 0; c < 8; c++) {
        int col = (c < 4) ? 4 * tx + c : 60 + 4 * tx + c;
        *(float4*)(s_buf + col * STRIDE + ty * 8) =
            make_float4(o1[0][c], o1[1][c], o1[2][c], o1[3][c]);
        *(float4*)(s_buf + col * STRIDE + ty * 8 + 4) =
            make_float4(o1[4][c], o1[5][c], o1[6][c], o1[7][c]);
    }

    u64 acc2[8][2];
    {
        float4 b = *(const float4*)(nb2 + 4 * tx);
        u64 i0 = packab(b.x, b.y), i1 = packab(b.z, b.w);
#pragma unroll
        for (int r = 0; r < 8; r++) { acc2[r][0] = i0; acc2[r][1] = i1; }
    }
    float4 pre2[2];
#pragma unroll
    for (int i = 0; i < 2; i++) {
        int off = i * 1024 + tid * 4;
        pre2[i] = *(const float4*)(nw2 + (off >> 6) * HH + (off & 63));
    }
#pragma unroll 1
    for (int kc = 0; kc < 4; kc++) {
        __syncthreads();
#pragma unroll
        for (int i = 0; i < 2; i++)
            *(float4*)(s_w + i * 1024 + tid * 4) = pre2[i];
        __syncthreads();
        if (kc < 3) {
#pragma unroll
            for (int i = 0; i < 2; i++) {
                int off = i * 1024 + tid * 4;
                pre2[i] = *(const float4*)(nw2 + ((kc + 1) * 32 + (off >> 6)) * HH + (off & 63));
            }
        }
        const float* ap = s_buf + (kc * 32) * STRIDE + ty * 8;
#pragma unroll 8
        for (int kk = 0; kk < 32; kk++) {
            float4 a0 = *(const float4*)(ap);
            float4 a1 = *(const float4*)(ap + 4);
            ap += STRIDE;
            ulonglong2 w01 = *(const ulonglong2*)(s_w + kk * HH + 4 * tx);
            float av[8] = {a0.x, a0.y, a0.z, a0.w, a1.x, a1.y, a1.z, a1.w};
#pragma unroll
            for (int r = 0; r < 8; r++) {
                u64 ar = pack2(av[r]);
                FMA2(acc2[r][0], ar, w01.x);
                FMA2(acc2[r][1], ar, w01.y);
            }
        }
    }
    float o2[8][4];
#pragma unroll
    for (int r = 0; r < 8; r++) {
        unpack2(acc2[r][0], o2[r][0], o2[r][1]);
        unpack2(acc2[r][1], o2[r][2], o2[r][3]);
    }
#pragma unroll
    for (int half = 0; half < 2; half++) {
        int n = n0 + 2 * ty + half;
        if (n < N) {
#pragma unroll
            for (int c = 0; c < 4; c++) {
                int col = 4 * tx + c;
                *(float4*)(out_h + ((size_t)n * HH + col) * T) =
                    make_float4(o2[half * 4 + 0][c], o2[half * 4 + 1][c],
                                o2[half * 4 + 2][c], o2[half * 4 + 3][c]);
            }
        }
    }
}

extern "C" void kernel_launch(void* const* d_in, const int* in_sizes, int n_in,
                              void* d_out, int out_size)
{
    const float* x   = (const float*)d_in[0];
    const float* h   = (const float*)d_in[1];
    const int*   ei  = (const int*)  d_in[2];
    const float* ea  = (const float*)d_in[3];
    const float* ew1 = (const float*)d_in[5];
    const float* eb1 = (const float*)d_in[6];
    const float* ew2 = (const float*)d_in[7];
    const float* eb2 = (const float*)d_in[8];
    const float* cw1 = (const float*)d_in[9];
    const float* cb1 = (const float*)d_in[10];
    const float* cw2 = (const float*)d_in[11];
    const float* cb2 = (const float*)d_in[12];
    const float* nw1 = (const float*)d_in[13];
    const float* nb1 = (const float*)d_in[14];
    const float* nw2 = (const float*)d_in[15];
    const float* nb2 = (const float*)d_in[16];

    int N = in_sizes[0] / (3 * T);
    int E = in_sizes[3] / (HE * T);

    float* out_x = (float*)d_out;
    float* out_h = out_x + (size_t)N * 3 * T;

    const int pre_smem  = (HH * STRIDE + 32 * HD) * sizeof(float);
    const int node_smem = (HD * STRIDE + 32 * HD) * sizeof(float);
    const int edge_smem = 157952;
    cudaFuncSetAttribute(pre_kernel,  cudaFuncAttributeMaxDynamicSharedMemorySize, pre_smem);
    cudaFuncSetAttribute(node_kernel, cudaFuncAttributeMaxDynamicSharedMemorySize, node_smem);
    cudaFuncSetAttribute(edge_kernel, cudaFuncAttributeMaxDynamicSharedMemorySize, edge_smem);

    zero_kernel<<<2048, 256>>>(N);
    wimg_kernel<<<(HD * HD) / 256, 256>>>(ew2, cw1);
    pre_kernel<<<(N + NPRE - 1) / NPRE, 256, pre_smem>>>(h, ew1, N);
    edge_kernel<<<(E + EPB - 1) / EPB, 256, edge_smem>>>(
        x, ei, ea, ew1, eb1, eb2, cb1, cw2, cb2, E);
    node_kernel<<<(N + NPB - 1) / NPB, 256, node_smem>>>(
        x, h, nw1, nb1, nw2, nb2, out_x, out_h, N);
}

// round 15
// speedup vs baseline: 1.1416x; 1.1416x over previous
#include <cuda_runtime.h>
#include <cuda_bf16.h>
#include <cstdint>

#define T    4
#define HH   64
#define HE   16
#define HD   128
#define EPB  32
#define ROWS 128
#define STRIDE 132
#define NPRE 32
#define NPB  32
#define MAXN 20000
#define EPSF 1e-8f
#define BROW 272          // bf16 operand row stride in bytes (136 bf16)

typedef unsigned long long u64;
typedef unsigned int u32;

// ---------------- device globals ----------------
__device__ float g_mi[MAXN * T * HD];          // [N, T, HD]
__device__ float g_agg[MAXN * 3 * T];
__device__ float g_cnt[MAXN];
__device__ float g_p1[(size_t)MAXN * T * HD];
__device__ float g_p2[(size_t)MAXN * T * HD];
__device__ float g_zerobias[HD];
// plain [n][k] bf16 hi/lo images of W2^T and CW1^T
__device__ __nv_bfloat16 g_w2hi[HD * HD], g_w2lo[HD * HD];
__device__ __nv_bfloat16 g_c1hi[HD * HD], g_c1lo[HD * HD];

__device__ __forceinline__ float silu_f(float v) {
    return v * __fdividef(1.0f, 1.0f + __expf(-v));
}

#define FMA2(d, a, b) asm("fma.rn.f32x2 %0, %1, %2, %0;" : "+l"(d) : "l"(a), "l"(b))
__device__ __forceinline__ u64 packab(float a, float b) {
    u64 r; asm("mov.b64 %0, {%1, %2};" : "=l"(r) : "f"(a), "f"(b)); return r;
}
__device__ __forceinline__ u64 pack2(float v) { return packab(v, v); }
__device__ __forceinline__ void unpack2(u64 v, float& lo, float& hi) {
    asm("mov.b64 {%0, %1}, %2;" : "=f"(lo), "=f"(hi) : "l"(v));
}
__device__ __forceinline__ u32 smem_u32(const void* p) {
    u32 a;
    asm("{ .reg .u64 t; cvta.to.shared.u64 t, %1; cvt.u32.u64 %0, t; }"
        : "=r"(a) : "l"(p));
    return a;
}
// bf16 pair hi/lo split
__device__ __forceinline__ void split2(float a, float b, u32& h, u32& l) {
    __nv_bfloat162 hp, lp;
    hp.x = __float2bfloat16(a); hp.y = __float2bfloat16(b);
    lp.x = __float2bfloat16(a - __bfloat162float(hp.x));
    lp.y = __float2bfloat16(b - __bfloat162float(hp.y));
    h = *reinterpret_cast<u32*>(&hp);
    l = *reinterpret_cast<u32*>(&lp);
}

#define LDMX4(r0, r1, r2, r3, addr) \
    asm volatile("ldmatrix.sync.aligned.m8n8.x4.shared.b16 {%0,%1,%2,%3}, [%4];" \
        : "=r"(r0), "=r"(r1), "=r"(r2), "=r"(r3) : "r"(addr))

#define MMA16816(d, a0, a1, a2, a3, b0, b1) \
    asm volatile("mma.sync.aligned.m16n8k16.row.col.f32.bf16.bf16.f32 " \
        "{%0,%1,%2,%3}, {%4,%5,%6,%7}, {%8,%9}, {%0,%1,%2,%3};" \
        : "+f"((d)[0]), "+f"((d)[1]), "+f"((d)[2]), "+f"((d)[3]) \
        : "r"(a0), "r"(a1), "r"(a2), "r"(a3), "r"(b0), "r"(b1))

#define REDV2(p, v0, v1) \
    asm volatile("red.global.add.v2.f32 [%0], {%1,%2};" \
                 :: "l"(p), "f"(v0), "f"(v1) : "memory")

// ---------------- small kernels ----------------
__global__ void zero_kernel(int n) {
    int stride = gridDim.x * blockDim.x;
    int base = blockIdx.x * blockDim.x + threadIdx.x;
    for (int i = base; i < n * HD * T; i += stride) g_mi[i] = 0.0f;
    for (int i = base; i < n * 3 * T;  i += stride) g_agg[i] = 0.0f;
    for (int i = base; i < n;          i += stride) g_cnt[i] = 0.0f;
}

__global__ void wimg_kernel(const float* __restrict__ w2, const float* __restrict__ cw1) {
    int idx = blockIdx.x * 256 + threadIdx.x;   // 16384
    int n = idx >> 7, k = idx & 127;
    float v2 = w2[k * HD + n];
    __nv_bfloat16 h2 = __float2bfloat16(v2);
    g_w2hi[idx] = h2;
    g_w2lo[idx] = __float2bfloat16(v2 - __bfloat162float(h2));
    float v3 = cw1[k * HD + n];
    __nv_bfloat16 h3 = __float2bfloat16(v3);
    g_c1hi[idx] = h3;
    g_c1lo[idx] = __float2bfloat16(v3 - __bfloat162float(h3));
}

// ---------------- FFMA2 GEMM tile (pre/node kernels) ----------------
template<int NCHUNK, int KLIM, bool ACT>
__device__ __forceinline__ void gemm_phase(
    const float* __restrict__ sA, float* __restrict__ sW,
    const float* __restrict__ gW, const float* __restrict__ gB,
    int tid, int tx, int ty, float (&out)[8][8])
{
    u64 acc[8][4];
    {
        float4 bA = *(const float4*)(gB + 4 * tx);
        float4 bB = *(const float4*)(gB + 64 + 4 * tx);
        u64 i0 = packab(bA.x, bA.y), i1 = packab(bA.z, bA.w);
        u64 i2 = packab(bB.x, bB.y), i3 = packab(bB.z, bB.w);
#pragma unroll
        for (int r = 0; r < 8; r++) {
            acc[r][0] = i0; acc[r][1] = i1; acc[r][2] = i2; acc[r][3] = i3;
        }
    }
    float4 pre[4];
#pragma unroll
    for (int i = 0; i < 4; i++) {
        int off = i * 1024 + tid * 4;
        int kg = off >> 7;
        pre[i] = (kg < KLIM) ? *(const float4*)(gW + kg * HD + (off & 127))
                             : make_float4(0.f, 0.f, 0.f, 0.f);
    }
#pragma unroll 1
    for (int kc = 0; kc < NCHUNK; kc++) {
        __syncthreads();
#pragma unroll
        for (int i = 0; i < 4; i++)
            *(float4*)(sW + i * 1024 + tid * 4) = pre[i];
        __syncthreads();
        if (kc + 1 < NCHUNK) {
#pragma unroll
            for (int i = 0; i < 4; i++) {
                int off = i * 1024 + tid * 4;
                int kg = (kc + 1) * 32 + (off >> 7);
                pre[i] = (kg < KLIM) ? *(const float4*)(gW + kg * HD + (off & 127))
                                     : make_float4(0.f, 0.f, 0.f, 0.f);
            }
        }
        const float* ap = sA + (kc * 32) * STRIDE + ty * 8;
#pragma unroll 8
        for (int kk = 0; kk < 32; kk++) {
            float4 a0 = *(const float4*)(ap);
            float4 a1 = *(const float4*)(ap + 4);
            ap += STRIDE;
            ulonglong2 bA = *(const ulonglong2*)(sW + kk * HD + 4 * tx);
            ulonglong2 bB = *(const ulonglong2*)(sW + kk * HD + 64 + 4 * tx);
            float av[8] = {a0.x, a0.y, a0.z, a0.w, a1.x, a1.y, a1.z, a1.w};
#pragma unroll
            for (int r = 0; r < 8; r++) {
                u64 ar = pack2(av[r]);
                FMA2(acc[r][0], ar, bA.x);
                FMA2(acc[r][1], ar, bA.y);
                FMA2(acc[r][2], ar, bB.x);
                FMA2(acc[r][3], ar, bB.y);
            }
        }
    }
#pragma unroll
    for (int r = 0; r < 8; r++)
#pragma unroll
        for (int cp = 0; cp < 4; cp++) {
            float lo, hi; unpack2(acc[r][cp], lo, hi);
            out[r][cp * 2]     = ACT ? silu_f(lo) : lo;
            out[r][cp * 2 + 1] = ACT ? silu_f(hi) : hi;
        }
}

// ---------------- P1/P2 precompute ----------------
__global__ __launch_bounds__(256, 2) void pre_kernel(
    const float* __restrict__ h, const float* __restrict__ w1, int N)
{
    extern __shared__ float sm[];
    float* s_h = sm;
    float* s_w = sm + HH * STRIDE;
    const int tid = threadIdx.x, tx = tid & 15, ty = tid >> 4;
    const int n0 = blockIdx.x * NPRE;
#pragma unroll
    for (int it = 0; it < 8; it++) {
        int idx = it * 256 + tid;
        int k = idx & 63, nl = idx >> 6;
        int node = n0 + nl; if (node >= N) node = N - 1;
        float4 v = *(const float4*)(h + ((size_t)node * HH + k) * T);
        *(float4*)(s_h + k * STRIDE + nl * 4) = v;
    }
    float o[8][8];
    gemm_phase<2, HH, false>(s_h, s_w, w1, g_zerobias, tid, tx, ty, o);
#pragma unroll
    for (int r = 0; r < 8; r++) {
        int row = ty * 8 + r;
        int node = n0 + (row >> 2), t = row & 3;
        if (node < N) {
            float* p = g_p1 + ((size_t)node * T + t) * HD;
            *(float4*)(p + 4 * tx)      = make_float4(o[r][0], o[r][1], o[r][2], o[r][3]);
            *(float4*)(p + 64 + 4 * tx) = make_float4(o[r][4], o[r][5], o[r][6], o[r][7]);
        }
    }
    gemm_phase<2, HH, false>(s_h, s_w, w1 + HH * HD, g_zerobias, tid, tx, ty, o);
#pragma unroll
    for (int r = 0; r < 8; r++) {
        int row = ty * 8 + r;
        int node = n0 + (row >> 2), t = row & 3;
        if (node < N) {
            float* p = g_p2 + ((size_t)node * T + t) * HD;
            *(float4*)(p + 4 * tx)      = make_float4(o[r][0], o[r][1], o[r][2], o[r][3]);
            *(float4*)(p + 64 + 4 * tx) = make_float4(o[r][4], o[r][5], o[r][6], o[r][7]);
        }
    }
}

// ---------------- edge kernel: 2 blocks/SM HMMA split-bf16 ----------------
// smem: sAhi(34816) | sAlo(34816) | sB(34816, single-buffered hi/lo)
//       s_ea+s_w1 overlay inside sB (dead after layer-1) | s_bias(1536)
__global__ __launch_bounds__(256, 2) void edge_kernel(
    const float* __restrict__ x,
    const int* __restrict__ ei, const float* __restrict__ ea,
    const float* __restrict__ w1, const float* __restrict__ b1,
    const float* __restrict__ b2, const float* __restrict__ cb1,
    const float* __restrict__ cw2, const float* __restrict__ cb2,
    int E)
{
    extern __shared__ __align__(16) char smc[];
    char* sAhi = smc;                        // 34816
    char* sAlo = smc + 34816;                // 34816
    char* sB   = smc + 69632;                // 34816 (B hi OR lo)
    float* s_ea   = (float*)(smc + 69632);           // overlay: 16 x STRIDE
    float* s_w1   = (float*)(smc + 69632 + 8448);    // overlay: 17 x 128
    float* s_bias = (float*)(smc + 104448);          // 384 floats

    __shared__ int   s_rown[EPB], s_coln[EPB];
    __shared__ float s_xij[EPB][3][T];
    __shared__ float s_n2[ROWS];

    const int tid = threadIdx.x, tx = tid & 15, ty = tid >> 4;
    const int wid = tid >> 5, t5 = tid & 31;
    const int e0 = blockIdx.x * EPB;

    const u32 sAhi_b = smem_u32(sAhi), sAlo_b = smem_u32(sAlo);
    const u32 sB_b = smem_u32(sB);

    if (tid < EPB) {
        int eg = e0 + tid; if (eg >= E) eg = E - 1;
        s_rown[tid] = ei[eg];
        s_coln[tid] = ei[E + eg];
    }
    // stage W1 rows 129..144 + row 128 (overlay region)
    for (int i = tid; i < 17 * 32; i += 256) {
        int k = i >> 5, cg = i & 31;
        int srcrow = (k == 16) ? 128 : (129 + k);
        *(float4*)(s_w1 + k * HD + cg * 4) = *(const float4*)(w1 + srcrow * HD + cg * 4);
    }
    if (tid < 128) {
        s_bias[tid]       = b2[tid];
        s_bias[128 + tid] = cb1[tid];
        s_bias[256 + tid] = cw2[tid];
    }
    __syncthreads();

    // edge_attr gather (overlay region)
#pragma unroll
    for (int it = 0; it < 2; it++) {
        int idx = it * 256 + tid;
        int k = idx & 15, e = idx >> 4;
        int eg = e0 + e; if (eg >= E) eg = E - 1;
        float4 v = *(const float4*)(ea + ((size_t)eg * HE + k) * T);
        *(float4*)(s_ea + k * STRIDE + e * 4) = v;
    }
    if (tid < ROWS) {
        int e = tid >> 2, t = tid & 3;
        int rn = s_rown[e], cn = s_coln[e];
        float n2 = 0.f;
#pragma unroll
        for (int d = 0; d < 3; d++) {
            float v = x[((size_t)rn * 3 + d) * T + t] - x[((size_t)cn * 3 + d) * T + t];
            s_xij[e][d][t] = v;
            n2 += v * v;
        }
        s_n2[tid] = n2;
    }
    __syncthreads();

    // ---- layer 1 (FFMA2), fused silu+split+store to sA ----
    {
        u64 acc[8][4];
        float4 bA = *(const float4*)(b1 + 4 * tx);
        float4 bB = *(const float4*)(b1 + 64 + 4 * tx);
        float4 wA = *(const float4*)(s_w1 + 16 * HD + 4 * tx);
        float4 wB = *(const float4*)(s_w1 + 16 * HD + 64 + 4 * tx);
#pragma unroll
        for (int r = 0; r < 8; r++) {
            int row = ty * 8 + r;
            int e = row >> 2, t = row & 3;
            const float* p1 = g_p1 + ((size_t)s_rown[e] * T + t) * HD;
            const float* p2 = g_p2 + ((size_t)s_coln[e] * T + t) * HD;
            float4 a1 = *(const float4*)(p1 + 4 * tx);
            float4 c1 = *(const float4*)(p1 + 64 + 4 * tx);
            float4 a2 = *(const float4*)(p2 + 4 * tx);
            float4 c2 = *(const float4*)(p2 + 64 + 4 * tx);
            float n2r = s_n2[row];
            acc[r][0] = packab(bA.x + a1.x + a2.x + n2r * wA.x,
                               bA.y + a1.y + a2.y + n2r * wA.y);
            acc[r][1] = packab(bA.z + a1.z + a2.z + n2r * wA.z,
                               bA.w + a1.w + a2.w + n2r * wA.w);
            acc[r][2] = packab(bB.x + c1.x + c2.x + n2r * wB.x,
                               bB.y + c1.y + c2.y + n2r * wB.y);
            acc[r][3] = packab(bB.z + c1.z + c2.z + n2r * wB.z,
                               bB.w + c1.w + c2.w + n2r * wB.w);
        }
        const float* ap = s_ea + ty * 8;
#pragma unroll
        for (int k = 0; k < HE; k++) {
            float4 a0 = *(const float4*)(ap);
            float4 a1 = *(const float4*)(ap + 4);
            ap += STRIDE;
            ulonglong2 wp0 = *(const ulonglong2*)(s_w1 + k * HD + 4 * tx);
            ulonglong2 wp1 = *(const ulonglong2*)(s_w1 + k * HD + 64 + 4 * tx);
            float av[8] = {a0.x, a0.y, a0.z, a0.w, a1.x, a1.y, a1.z, a1.w};
#pragma unroll
            for (int r = 0; r < 8; r++) {
                u64 ar = pack2(av[r]);
                FMA2(acc[r][0], ar, wp0.x);
                FMA2(acc[r][1], ar, wp0.y);
                FMA2(acc[r][2], ar, wp1.x);
                FMA2(acc[r][3], ar, wp1.y);
            }
        }
        // fused: unpack -> silu -> split -> store (no o1 array)
#pragma unroll
        for (int r = 0; r < 8; r++) {
            int row = ty * 8 + r;
#pragma unroll
            for (int cp = 0; cp < 4; cp++) {
                float lo, hi; unpack2(acc[r][cp], lo, hi);
                lo = silu_f(lo); hi = silu_f(hi);
                int col = (cp < 2) ? (4 * tx + 2 * cp) : (64 + 4 * tx + 2 * (cp - 2));
                u32 hh, ll;
                split2(lo, hi, hh, ll);
                *(u32*)(sAhi + row * BROW + col * 2) = hh;
                *(u32*)(sAlo + row * BROW + col * 2) = ll;
            }
        }
    }
    __syncthreads();                 // layer-1 reads of overlay done

    // ldmatrix per-thread offsets
    const u32 aoff = (u32)((wid * 16 + (t5 & 15)) * BROW + ((t5 & 16) ? 16 : 0));
    const u32 boff = (u32)(((t5 & 7) + ((t5 >> 4) << 3)) * BROW + ((t5 & 8) << 1));

    // B stage helper lambda-ish macro: copy 128x256B image into 272B-stride sB
#define STAGE_B(src) do { \
        int row_ = tid >> 1, half_ = tid & 1; \
        const float4* s_ = (const float4*)((const char*)(src) + row_ * 256 + half_ * 128); \
        float4* d_ = (float4*)(sB + row_ * BROW + half_ * 128); \
        d_[0] = s_[0]; d_[1] = s_[1]; d_[2] = s_[2]; d_[3] = s_[3]; \
        d_[4] = s_[4]; d_[5] = s_[5]; d_[6] = s_[6]; d_[7] = s_[7]; \
    } while (0)

    float d[16][4];
#pragma unroll
    for (int n = 0; n < 16; n++)
#pragma unroll
        for (int q = 0; q < 4; q++) d[n][q] = 0.f;

    // ---- GEMM1a: (Ahi+Alo) @ W2hi ----
    STAGE_B(g_w2hi);
    __syncthreads();
#pragma unroll 1
    for (int ks = 0; ks < 8; ks++) {
        u32 ah[4], al[4];
        LDMX4(ah[0], ah[1], ah[2], ah[3], sAhi_b + aoff + ks * 32);
        LDMX4(al[0], al[1], al[2], al[3], sAlo_b + aoff + ks * 32);
#pragma unroll
        for (int j = 0; j < 8; j++) {
            u32 b0, b1, b2r, b3;
            LDMX4(b0, b1, b2r, b3, sB_b + boff + j * (16 * BROW) + ks * 32);
            MMA16816(d[2 * j],     ah[0], ah[1], ah[2], ah[3], b0, b1);
            MMA16816(d[2 * j + 1], ah[0], ah[1], ah[2], ah[3], b2r, b3);
            MMA16816(d[2 * j],     al[0], al[1], al[2], al[3], b0, b1);
            MMA16816(d[2 * j + 1], al[0], al[1], al[2], al[3], b2r, b3);
        }
    }
    __syncthreads();
    // ---- GEMM1b: Ahi @ W2lo ----
    STAGE_B(g_w2lo);
    __syncthreads();
#pragma unroll 1
    for (int ks = 0; ks < 8; ks++) {
        u32 ah[4];
        LDMX4(ah[0], ah[1], ah[2], ah[3], sAhi_b + aoff + ks * 32);
#pragma unroll
        for (int j = 0; j < 8; j++) {
            u32 b0, b1, b2r, b3;
            LDMX4(b0, b1, b2r, b3, sB_b + boff + j * (16 * BROW) + ks * 32);
            MMA16816(d[2 * j],     ah[0], ah[1], ah[2], ah[3], b0, b1);
            MMA16816(d[2 * j + 1], ah[0], ah[1], ah[2], ah[3], b2r, b3);
        }
    }
    __syncthreads();                 // B ldmatrix done before next restage;
                                     // also A reads done before overwrite below

    // ---- readback GEMM1: +b2, silu, scatter m_i, store A2 to sA ----
    const int g = t5 >> 2, tg = t5 & 3;
    const int rowA = wid * 16 + g, rowB = rowA + 8;
    const int eA = rowA >> 2, tA = rowA & 3;
    const int eB = rowB >> 2, tB = rowB & 3;
    const bool okA = (e0 + eA) < E, okB = (e0 + eB) < E;
    float* mA = g_mi + ((size_t)s_rown[eA] * T + tA) * HD;
    float* mB = g_mi + ((size_t)s_rown[eB] * T + tB) * HD;

#pragma unroll
    for (int n = 0; n < 16; n++) {
        int c = 8 * n + 2 * tg;
        float v0 = silu_f(d[n][0] + s_bias[c]);
        float v1 = silu_f(d[n][1] + s_bias[c + 1]);
        float v2 = silu_f(d[n][2] + s_bias[c]);
        float v3 = silu_f(d[n][3] + s_bias[c + 1]);
        if (okA) REDV2(mA + c, v0, v1);
        if (okB) REDV2(mB + c, v2, v3);
        u32 hh, ll;
        split2(v0, v1, hh, ll);
        *(u32*)(sAhi + rowA * BROW + c * 2) = hh;
        *(u32*)(sAlo + rowA * BROW + c * 2) = ll;
        split2(v2, v3, hh, ll);
        *(u32*)(sAhi + rowB * BROW + c * 2) = hh;
        *(u32*)(sAlo + rowB * BROW + c * 2) = ll;
        d[n][0] = d[n][1] = d[n][2] = d[n][3] = 0.f;
    }
    __syncthreads();

    // ---- GEMM2a: (A2hi+A2lo) @ CW1hi ----
    STAGE_B(g_c1hi);
    __syncthreads();
#pragma unroll 1
    for (int ks = 0; ks < 8; ks++) {
        u32 ah[4], al[4];
        LDMX4(ah[0], ah[1], ah[2], ah[3], sAhi_b + aoff + ks * 32);
        LDMX4(al[0], al[1], al[2], al[3], sAlo_b + aoff + ks * 32);
#pragma unroll
        for (int j = 0; j < 8; j++) {
            u32 b0, b1, b2r, b3;
            LDMX4(b0, b1, b2r, b3, sB_b + boff + j * (16 * BROW) + ks * 32);
            MMA16816(d[2 * j],     ah[0], ah[1], ah[2], ah[3], b0, b1);
            MMA16816(d[2 * j + 1], ah[0], ah[1], ah[2], ah[3], b2r, b3);
            MMA16816(d[2 * j],     al[0], al[1], al[2], al[3], b0, b1);
            MMA16816(d[2 * j + 1], al[0], al[1], al[2], al[3], b2r, b3);
        }
    }
    __syncthreads();
    // ---- GEMM2b: A2hi @ CW1lo ----
    STAGE_B(g_c1lo);
    __syncthreads();
#pragma unroll 1
    for (int ks = 0; ks < 8; ks++) {
        u32 ah[4];
        LDMX4(ah[0], ah[1], ah[2], ah[3], sAhi_b + aoff + ks * 32);
#pragma unroll
        for (int j = 0; j < 8; j++) {
            u32 b0, b1, b2r, b3;
            LDMX4(b0, b1, b2r, b3, sB_b + boff + j * (16 * BROW) + ks * 32);
            MMA16816(d[2 * j],     ah[0], ah[1], ah[2], ah[3], b0, b1);
            MMA16816(d[2 * j + 1], ah[0], ah[1], ah[2], ah[3], b2r, b3);
        }
    }

    // ---- readback GEMM2: silu, dot cw2, quad-reduce, coord epilogue ----
    {
        float pA = 0.f, pB = 0.f;
#pragma unroll
        for (int n = 0; n < 16; n++) {
            int c = 8 * n + 2 * tg;
            pA += silu_f(d[n][0] + s_bias[128 + c])     * s_bias[256 + c];
            pA += silu_f(d[n][1] + s_bias[128 + c + 1]) * s_bias[256 + c + 1];
            pB += silu_f(d[n][2] + s_bias[128 + c])     * s_bias[256 + c];
            pB += silu_f(d[n][3] + s_bias[128 + c + 1]) * s_bias[256 + c + 1];
        }
        pA += __shfl_xor_sync(0xffffffffu, pA, 1);
        pA += __shfl_xor_sync(0xffffffffu, pA, 2);
        pB += __shfl_xor_sync(0xffffffffu, pB, 1);
        pB += __shfl_xor_sync(0xffffffffu, pB, 2);
        if (tg == 0) {
            float cb2v = cb2[0];
#pragma unroll
            for (int half = 0; half < 2; half++) {
                int row = half ? rowB : rowA;
                float p = half ? pB : pA;
                int e = row >> 2, t = row & 3;
                if (e0 + e < E) {
                    float cval = (p + cb2v) *
                        __fdividef(1.0f, sqrtf(s_n2[row] + EPSF) + 1.0f);
                    int node = s_rown[e];
#pragma unroll
                    for (int dd = 0; dd < 3; dd++)
                        atomicAdd(&g_agg[((size_t)node * 3 + dd) * T + t],
                                  cval * s_xij[e][dd][t]);
                    if (t == 0) atomicAdd(&g_cnt[node], 1.0f);
                }
            }
        }
    }
#undef STAGE_B
}

// ---------------- node kernel ([N,T,HD] g_mi gather) ----------------
__global__ __launch_bounds__(256, 2) void node_kernel(
    const float* __restrict__ x, const float* __restrict__ h,
    const float* __restrict__ nw1, const float* __restrict__ nb1,
    const float* __restrict__ nw2, const float* __restrict__ nb2,
    float* __restrict__ out_x, float* __restrict__ out_h, int N)
{
    extern __shared__ float sm[];
    float* s_buf = sm;
    float* s_w   = sm + HD * STRIDE;

    const int tid = threadIdx.x, tx = tid & 15, ty = tid >> 4;
    const int n0 = blockIdx.x * NPB;

#pragma unroll
    for (int it = 0; it < 2; it++) {
        int idx = it * 256 + tid;
        if (idx < NPB * 12) {
            int n = n0 + idx / 12;
            if (n < N) {
                int rem = idx % 12, d = rem >> 2, t = rem & 3;
                float cv = fmaxf(g_cnt[n], 1.0f);
                int off = (n * 3 + d) * T + t;
                out_x[off] = x[off] + g_agg[off] * __fdividef(1.0f, cv);
            }
        }
    }

#pragma unroll
    for (int it = 0; it < 8; it++) {
        int idx = it * 256 + tid;
        int k = idx & 63, nl = idx >> 6;
        int node = n0 + nl; if (node >= N) node = N - 1;
        float4 v = *(const float4*)(h + ((size_t)node * HH + k) * T);
        *(float4*)(s_buf + k * STRIDE + nl * 4) = v;
    }
#pragma unroll
    for (int it = 0; it < 8; it++) {
        int idx = it * 256 + tid;
        int kq = idx & 15, t = (idx >> 4) & 3, nl = idx >> 6;
        int node = n0 + nl; if (node >= N) node = N - 1;
        float4 v = *(const float4*)(g_mi + ((size_t)node * T + t) * HD + kq * 4);
        s_buf[(HH + kq * 4 + 0) * STRIDE + nl * 4 + t] = v.x;
        s_buf[(HH + kq * 4 + 1) * STRIDE + nl * 4 + t] = v.y;
        s_buf[(HH + kq * 4 + 2) * STRIDE + nl * 4 + t] = v.z;
        s_buf[(HH + kq * 4 + 3) * STRIDE + nl * 4 + t] = v.w;
    }

    u64 acc[8][4];
    {
        float4 bA = *(const float4*)(nb1 + 4 * tx);
        float4 bB = *(const float4*)(nb1 + 64 + 4 * tx);
        u64 i0 = packab(bA.x, bA.y), i1 = packab(bA.z, bA.w);
        u64 i2 = packab(bB.x, bB.y), i3 = packab(bB.z, bB.w);
#pragma unroll
        for (int r = 0; r < 8; r++) {
            acc[r][0] = i0; acc[r][1] = i1; acc[r][2] = i2; acc[r][3] = i3;
        }
    }
    float4 pre[4];
#pragma unroll
    for (int i = 0; i < 4; i++) {
        int off = i * 1024 + tid * 4;
        pre[i] = *(const float4*)(nw1 + (off >> 7) * HD + (off & 127));
    }
#pragma unroll 1
    for (int kc = 0; kc < 4; kc++) {
        __syncthreads();
#pragma unroll
        for (int i = 0; i < 4; i++)
            *(float4*)(s_w + i * 1024 + tid * 4) = pre[i];
        __syncthreads();
        {
            int kbase = (kc + 1) * 32;
            if (kbase < 192) {
#pragma unroll
                for (int i = 0; i < 4; i++) {
                    int off = i * 1024 + tid * 4;
                    pre[i] = *(const float4*)(nw1 + (kbase + (off >> 7)) * HD + (off & 127));
                }
            }
        }
        const float* ap = s_buf + (kc * 32) * STRIDE + ty * 8;
#pragma unroll 8
        for (int kk = 0; kk < 32; kk++) {
            float4 a0 = *(const float4*)(ap);
            float4 a1 = *(const float4*)(ap + 4);
            ap += STRIDE;
            ulonglong2 bA = *(const ulonglong2*)(s_w + kk * HD + 4 * tx);
            ulonglong2 bB = *(const ulonglong2*)(s_w + kk * HD + 64 + 4 * tx);
            float av[8] = {a0.x, a0.y, a0.z, a0.w, a1.x, a1.y, a1.z, a1.w};
#pragma unroll
            for (int r = 0; r < 8; r++) {
                u64 ar = pack2(av[r]);
                FMA2(acc[r][0], ar, bA.x);
                FMA2(acc[r][1], ar, bA.y);
                FMA2(acc[r][2], ar, bB.x);
                FMA2(acc[r][3], ar, bB.y);
            }
        }
    }
    __syncthreads();

#pragma unroll
    for (int it = 0; it < 8; it++) {
        int idx = it * 256 + tid;
        int kq = idx & 15, t = (idx >> 4) & 3, nl = idx >> 6;
        int node = n0 + nl; if (node >= N) node = N - 1;
        float4 v = *(const float4*)(g_mi + ((size_t)node * T + t) * HD + 64 + kq * 4);
        s_buf[(kq * 4 + 0) * STRIDE + nl * 4 + t] = v.x;
        s_buf[(kq * 4 + 1) * STRIDE + nl * 4 + t] = v.y;
        s_buf[(kq * 4 + 2) * STRIDE + nl * 4 + t] = v.z;
        s_buf[(kq * 4 + 3) * STRIDE + nl * 4 + t] = v.w;
    }
#pragma unroll 1
    for (int kc = 0; kc < 2; kc++) {
        __syncthreads();
#pragma unroll
        for (int i = 0; i < 4; i++)
            *(float4*)(s_w + i * 1024 + tid * 4) = pre[i];
        __syncthreads();
        if (kc == 0) {
#pragma unroll
            for (int i = 0; i < 4; i++) {
                int off = i * 1024 + tid * 4;
                pre[i] = *(const float4*)(nw1 + (160 + (off >> 7)) * HD + (off & 127));
            }
        }
        const float* ap = s_buf + (kc * 32) * STRIDE + ty * 8;
#pragma unroll 8
        for (int kk = 0; kk < 32; kk++) {
            float4 a0 = *(const float4*)(ap);
            float4 a1 = *(const float4*)(ap + 4);
            ap += STRIDE;
            ulonglong2 bA = *(const ulonglong2*)(s_w + kk * HD + 4 * tx);
            ulonglong2 bB = *(const ulonglong2*)(s_w + kk * HD + 64 + 4 * tx);
            float av[8] = {a0.x, a0.y, a0.z, a0.w, a1.x, a1.y, a1.z, a1.w};
#pragma unroll
            for (int r = 0; r < 8; r++) {
                u64 ar = pack2(av[r]);
                FMA2(acc[r][0], ar, bA.x);
                FMA2(acc[r][1], ar, bA.y);
                FMA2(acc[r][2], ar, bB.x);
                FMA2(acc[r][3], ar, bB.y);
            }
        }
    }

    float o1[8][8];
#pragma unroll
    for (int r = 0; r < 8; r++)
#pragma unroll
        for (int cp = 0; cp < 4; cp++) {
            float lo, hi; unpack2(acc[r][cp], lo, hi);
            o1[r][2 * cp]     = silu_f(lo);
            o1[r][2 * cp + 1] = silu_f(hi);
        }
    __syncthreads();
#pragma unroll
    for (int c = 0; c < 8; c++) {
        int col = (c < 4) ? 4 * tx + c : 60 + 4 * tx + c;
        *(float4*)(s_buf + col * STRIDE + ty * 8) =
            make_float4(o1[0][c], o1[1][c], o1[2][c], o1[3][c]);
        *(float4*)(s_buf + col * STRIDE + ty * 8 + 4) =
            make_float4(o1[4][c], o1[5][c], o1[6][c], o1[7][c]);
    }

    u64 acc2[8][2];
    {
        float4 b = *(const float4*)(nb2 + 4 * tx);
        u64 i0 = packab(b.x, b.y), i1 = packab(b.z, b.w);
#pragma unroll
        for (int r = 0; r < 8; r++) { acc2[r][0] = i0; acc2[r][1] = i1; }
    }
    float4 pre2[2];
#pragma unroll
    for (int i = 0; i < 2; i++) {
        int off = i * 1024 + tid * 4;
        pre2[i] = *(const float4*)(nw2 + (off >> 6) * HH + (off & 63));
    }
#pragma unroll 1
    for (int kc = 0; kc < 4; kc++) {
        __syncthreads();
#pragma unroll
        for (int i = 0; i < 2; i++)
            *(float4*)(s_w + i * 1024 + tid * 4) = pre2[i];
        __syncthreads();
        if (kc < 3) {
#pragma unroll
            for (int i = 0; i < 2; i++) {
                int off = i * 1024 + tid * 4;
                pre2[i] = *(const float4*)(nw2 + ((kc + 1) * 32 + (off >> 6)) * HH + (off & 63));
            }
        }
        const float* ap = s_buf + (kc * 32) * STRIDE + ty * 8;
#pragma unroll 8
        for (int kk = 0; kk < 32; kk++) {
            float4 a0 = *(const float4*)(ap);
            float4 a1 = *(const float4*)(ap + 4);
            ap += STRIDE;
            ulonglong2 w01 = *(const ulonglong2*)(s_w + kk * HH + 4 * tx);
            float av[8] = {a0.x, a0.y, a0.z, a0.w, a1.x, a1.y, a1.z, a1.w};
#pragma unroll
            for (int r = 0; r < 8; r++) {
                u64 ar = pack2(av[r]);
                FMA2(acc2[r][0], ar, w01.x);
                FMA2(acc2[r][1], ar, w01.y);
            }
        }
    }
    float o2[8][4];
#pragma unroll
    for (int r = 0; r < 8; r++) {
        unpack2(acc2[r][0], o2[r][0], o2[r][1]);
        unpack2(acc2[r][1], o2[r][2], o2[r][3]);
    }
#pragma unroll
    for (int half = 0; half < 2; half++) {
        int n = n0 + 2 * ty + half;
        if (n < N) {
#pragma unroll
            for (int c = 0; c < 4; c++) {
                int col = 4 * tx + c;
                *(float4*)(out_h + ((size_t)n * HH + col) * T) =
                    make_float4(o2[half * 4 + 0][c], o2[half * 4 + 1][c],
                                o2[half * 4 + 2][c], o2[half * 4 + 3][c]);
            }
        }
    }
}

extern "C" void kernel_launch(void* const* d_in, const int* in_sizes, int n_in,
                              void* d_out, int out_size)
{
    const float* x   = (const float*)d_in[0];
    const float* h   = (const float*)d_in[1];
    const int*   ei  = (const int*)  d_in[2];
    const float* ea  = (const float*)d_in[3];
    const float* ew1 = (const float*)d_in[5];
    const float* eb1 = (const float*)d_in[6];
    const float* ew2 = (const float*)d_in[7];
    const float* eb2 = (const float*)d_in[8];
    const float* cw1 = (const float*)d_in[9];
    const float* cb1 = (const float*)d_in[10];
    const float* cw2 = (const float*)d_in[11];
    const float* cb2 = (const float*)d_in[12];
    const float* nw1 = (const float*)d_in[13];
    const float* nb1 = (const float*)d_in[14];
    const float* nw2 = (const float*)d_in[15];
    const float* nb2 = (const float*)d_in[16];

    int N = in_sizes[0] / (3 * T);
    int E = in_sizes[3] / (HE * T);

    float* out_x = (float*)d_out;
    float* out_h = out_x + (size_t)N * 3 * T;

    const int pre_smem  = (HH * STRIDE + 32 * HD) * sizeof(float);
    const int node_smem = (HD * STRIDE + 32 * HD) * sizeof(float);
    const int edge_smem = 105984;
    cudaFuncSetAttribute(pre_kernel,  cudaFuncAttributeMaxDynamicSharedMemorySize, pre_smem);
    cudaFuncSetAttribute(node_kernel, cudaFuncAttributeMaxDynamicSharedMemorySize, node_smem);
    cudaFuncSetAttribute(edge_kernel, cudaFuncAttributeMaxDynamicSharedMemorySize, edge_smem);

    zero_kernel<<<2048, 256>>>(N);
    wimg_kernel<<<(HD * HD) / 256, 256>>>(ew2, cw1);
    pre_kernel<<<(N + NPRE - 1) / NPRE, 256, pre_smem>>>(h, ew1, N);
    edge_kernel<<<(E + EPB - 1) / EPB, 256, edge_smem>>>(
        x, ei, ea, ew1, eb1, eb2, cb1, cw2, cb2, E);
    node_kernel<<<(N + NPB - 1) / NPB, 256, node_smem>>>(
        x, h, nw1, nb1, nw2, nb2, out_x, out_h, N);
}

// round 16
// speedup vs baseline: 1.1714x; 1.0261x over previous
#include <cuda_runtime.h>
#include <cuda_bf16.h>
#include <cstdint>

#define T    4
#define HH   64
#define HE   16
#define HD   128
#define EPB  32
#define ROWS 128
#define STRIDE 132
#define NPRE 32
#define NPB  32
#define MAXN 20000
#define EPSF 1e-8f
#define BROW 272          // bf16 operand row stride in bytes (136 bf16)

typedef unsigned long long u64;
typedef unsigned int u32;

// ---------------- device globals ----------------
__device__ float g_mi[MAXN * T * HD];          // [N, T, HD]
__device__ float g_agg[MAXN * 3 * T];
__device__ float g_cnt[MAXN];
__device__ float g_p1[(size_t)MAXN * T * HD];
__device__ float g_p2[(size_t)MAXN * T * HD];
__device__ float g_zerobias[HD];
// plain [n][k] bf16 hi/lo images of W2^T and CW1^T
__device__ __nv_bfloat16 g_w2hi[HD * HD], g_w2lo[HD * HD];
__device__ __nv_bfloat16 g_c1hi[HD * HD], g_c1lo[HD * HD];

__device__ __forceinline__ float silu_f(float v) {
    return v * __fdividef(1.0f, 1.0f + __expf(-v));
}

#define FMA2(d, a, b) asm("fma.rn.f32x2 %0, %1, %2, %0;" : "+l"(d) : "l"(a), "l"(b))
__device__ __forceinline__ u64 packab(float a, float b) {
    u64 r; asm("mov.b64 %0, {%1, %2};" : "=l"(r) : "f"(a), "f"(b)); return r;
}
__device__ __forceinline__ u64 pack2(float v) { return packab(v, v); }
__device__ __forceinline__ void unpack2(u64 v, float& lo, float& hi) {
    asm("mov.b64 {%0, %1}, %2;" : "=f"(lo), "=f"(hi) : "l"(v));
}
__device__ __forceinline__ u32 smem_u32(const void* p) {
    u32 a;
    asm("{ .reg .u64 t; cvta.to.shared.u64 t, %1; cvt.u32.u64 %0, t; }"
        : "=r"(a) : "l"(p));
    return a;
}
__device__ __forceinline__ void split2(float a, float b, u32& h, u32& l) {
    __nv_bfloat162 hp, lp;
    hp.x = __float2bfloat16(a); hp.y = __float2bfloat16(b);
    lp.x = __float2bfloat16(a - __bfloat162float(hp.x));
    lp.y = __float2bfloat16(b - __bfloat162float(hp.y));
    h = *reinterpret_cast<u32*>(&hp);
    l = *reinterpret_cast<u32*>(&lp);
}

#define LDMX4(r0, r1, r2, r3, addr) \
    asm volatile("ldmatrix.sync.aligned.m8n8.x4.shared.b16 {%0,%1,%2,%3}, [%4];" \
        : "=r"(r0), "=r"(r1), "=r"(r2), "=r"(r3) : "r"(addr))

#define MMA16816(d, a0, a1, a2, a3, b0, b1) \
    asm volatile("mma.sync.aligned.m16n8k16.row.col.f32.bf16.bf16.f32 " \
        "{%0,%1,%2,%3}, {%4,%5,%6,%7}, {%8,%9}, {%0,%1,%2,%3};" \
        : "+f"((d)[0]), "+f"((d)[1]), "+f"((d)[2]), "+f"((d)[3]) \
        : "r"(a0), "r"(a1), "r"(a2), "r"(a3), "r"(b0), "r"(b1))

#define REDV2(p, v0, v1) \
    asm volatile("red.global.add.v2.f32 [%0], {%1,%2};" \
                 :: "l"(p), "f"(v0), "f"(v1) : "memory")

// ---------------- small kernels ----------------
__global__ void zero_kernel(int n) {
    int stride = gridDim.x * blockDim.x;
    int base = blockIdx.x * blockDim.x + threadIdx.x;
    for (int i = base; i < n * HD * T; i += stride) g_mi[i] = 0.0f;
    for (int i = base; i < n * 3 * T;  i += stride) g_agg[i] = 0.0f;
    for (int i = base; i < n;          i += stride) g_cnt[i] = 0.0f;
}

__global__ void wimg_kernel(const float* __restrict__ w2, const float* __restrict__ cw1) {
    int idx = blockIdx.x * 256 + threadIdx.x;   // 16384
    int n = idx >> 7, k = idx & 127;
    float v2 = w2[k * HD + n];
    __nv_bfloat16 h2 = __float2bfloat16(v2);
    g_w2hi[idx] = h2;
    g_w2lo[idx] = __float2bfloat16(v2 - __bfloat162float(h2));
    float v3 = cw1[k * HD + n];
    __nv_bfloat16 h3 = __float2bfloat16(v3);
    g_c1hi[idx] = h3;
    g_c1lo[idx] = __float2bfloat16(v3 - __bfloat162float(h3));
}

// ---------------- FFMA2 GEMM tile (pre/node kernels) ----------------
template<int NCHUNK, int KLIM, bool ACT>
__device__ __forceinline__ void gemm_phase(
    const float* __restrict__ sA, float* __restrict__ sW,
    const float* __restrict__ gW, const float* __restrict__ gB,
    int tid, int tx, int ty, float (&out)[8][8])
{
    u64 acc[8][4];
    {
        float4 bA = *(const float4*)(gB + 4 * tx);
        float4 bB = *(const float4*)(gB + 64 + 4 * tx);
        u64 i0 = packab(bA.x, bA.y), i1 = packab(bA.z, bA.w);
        u64 i2 = packab(bB.x, bB.y), i3 = packab(bB.z, bB.w);
#pragma unroll
        for (int r = 0; r < 8; r++) {
            acc[r][0] = i0; acc[r][1] = i1; acc[r][2] = i2; acc[r][3] = i3;
        }
    }
    float4 pre[4];
#pragma unroll
    for (int i = 0; i < 4; i++) {
        int off = i * 1024 + tid * 4;
        int kg = off >> 7;
        pre[i] = (kg < KLIM) ? *(const float4*)(gW + kg * HD + (off & 127))
                             : make_float4(0.f, 0.f, 0.f, 0.f);
    }
#pragma unroll 1
    for (int kc = 0; kc < NCHUNK; kc++) {
        __syncthreads();
#pragma unroll
        for (int i = 0; i < 4; i++)
            *(float4*)(sW + i * 1024 + tid * 4) = pre[i];
        __syncthreads();
        if (kc + 1 < NCHUNK) {
#pragma unroll
            for (int i = 0; i < 4; i++) {
                int off = i * 1024 + tid * 4;
                int kg = (kc + 1) * 32 + (off >> 7);
                pre[i] = (kg < KLIM) ? *(const float4*)(gW + kg * HD + (off & 127))
                                     : make_float4(0.f, 0.f, 0.f, 0.f);
            }
        }
        const float* ap = sA + (kc * 32) * STRIDE + ty * 8;
#pragma unroll 8
        for (int kk = 0; kk < 32; kk++) {
            float4 a0 = *(const float4*)(ap);
            float4 a1 = *(const float4*)(ap + 4);
            ap += STRIDE;
            ulonglong2 bA = *(const ulonglong2*)(sW + kk * HD + 4 * tx);
            ulonglong2 bB = *(const ulonglong2*)(sW + kk * HD + 64 + 4 * tx);
            float av[8] = {a0.x, a0.y, a0.z, a0.w, a1.x, a1.y, a1.z, a1.w};
#pragma unroll
            for (int r = 0; r < 8; r++) {
                u64 ar = pack2(av[r]);
                FMA2(acc[r][0], ar, bA.x);
                FMA2(acc[r][1], ar, bA.y);
                FMA2(acc[r][2], ar, bB.x);
                FMA2(acc[r][3], ar, bB.y);
            }
        }
    }
#pragma unroll
    for (int r = 0; r < 8; r++)
#pragma unroll
        for (int cp = 0; cp < 4; cp++) {
            float lo, hi; unpack2(acc[r][cp], lo, hi);
            out[r][cp * 2]     = ACT ? silu_f(lo) : lo;
            out[r][cp * 2 + 1] = ACT ? silu_f(hi) : hi;
        }
}

// ---------------- P1/P2 precompute ----------------
__global__ __launch_bounds__(256, 2) void pre_kernel(
    const float* __restrict__ h, const float* __restrict__ w1, int N)
{
    extern __shared__ float sm[];
    float* s_h = sm;
    float* s_w = sm + HH * STRIDE;
    const int tid = threadIdx.x, tx = tid & 15, ty = tid >> 4;
    const int n0 = blockIdx.x * NPRE;
#pragma unroll
    for (int it = 0; it < 8; it++) {
        int idx = it * 256 + tid;
        int k = idx & 63, nl = idx >> 6;
        int node = n0 + nl; if (node >= N) node = N - 1;
        float4 v = *(const float4*)(h + ((size_t)node * HH + k) * T);
        *(float4*)(s_h + k * STRIDE + nl * 4) = v;
    }
    float o[8][8];
    gemm_phase<2, HH, false>(s_h, s_w, w1, g_zerobias, tid, tx, ty, o);
#pragma unroll
    for (int r = 0; r < 8; r++) {
        int row = ty * 8 + r;
        int node = n0 + (row >> 2), t = row & 3;
        if (node < N) {
            float* p = g_p1 + ((size_t)node * T + t) * HD;
            *(float4*)(p + 4 * tx)      = make_float4(o[r][0], o[r][1], o[r][2], o[r][3]);
            *(float4*)(p + 64 + 4 * tx) = make_float4(o[r][4], o[r][5], o[r][6], o[r][7]);
        }
    }
    gemm_phase<2, HH, false>(s_h, s_w, w1 + HH * HD, g_zerobias, tid, tx, ty, o);
#pragma unroll
    for (int r = 0; r < 8; r++) {
        int row = ty * 8 + r;
        int node = n0 + (row >> 2), t = row & 3;
        if (node < N) {
            float* p = g_p2 + ((size_t)node * T + t) * HD;
            *(float4*)(p + 4 * tx)      = make_float4(o[r][0], o[r][1], o[r][2], o[r][3]);
            *(float4*)(p + 64 + 4 * tx) = make_float4(o[r][4], o[r][5], o[r][6], o[r][7]);
        }
    }
}

// ---------------- edge kernel: single-pass split-bf16 HMMA ----------------
// smem: sAhi(34816) | sBhi(34816) | sB2(34816: Alo then Blo; overlay ea/w1)
//       s_bias(1536)
__global__ __launch_bounds__(256, 2) void edge_kernel(
    const float* __restrict__ x,
    const int* __restrict__ ei, const float* __restrict__ ea,
    const float* __restrict__ w1, const float* __restrict__ b1,
    const float* __restrict__ b2, const float* __restrict__ cb1,
    const float* __restrict__ cw2, const float* __restrict__ cb2,
    int E)
{
    extern __shared__ __align__(16) char smc[];
    char* sAhi = smc;                        // 34816
    char* sBhi = smc + 34816;                // 34816
    char* sB2  = smc + 69632;                // 34816 (Alo, then Blo)
    float* s_ea   = (float*)(smc + 69632);           // overlay in sB2
    float* s_w1   = (float*)(smc + 69632 + 8448);    // overlay in sB2
    float* s_bias = (float*)(smc + 104448);          // 384 floats

    __shared__ int   s_rown[EPB], s_coln[EPB];
    __shared__ float s_xij[EPB][3][T];
    __shared__ float s_n2[ROWS];

    const int tid = threadIdx.x, tx = tid & 15, ty = tid >> 4;
    const int wid = tid >> 5, t5 = tid & 31;
    const int e0 = blockIdx.x * EPB;

    const u32 sAhi_b = smem_u32(sAhi), sBhi_b = smem_u32(sBhi);
    const u32 sB2_b = smem_u32(sB2);

    if (tid < EPB) {
        int eg = e0 + tid; if (eg >= E) eg = E - 1;
        s_rown[tid] = ei[eg];
        s_coln[tid] = ei[E + eg];
    }
    // stage Bhi = W2hi early (own buffer; overlaps later gathers)
    {
        int row_ = tid >> 1, half_ = tid & 1;
        const float4* s_ = (const float4*)((const char*)g_w2hi + row_ * 256 + half_ * 128);
        float4* d_ = (float4*)(sBhi + row_ * BROW + half_ * 128);
#pragma unroll
        for (int q = 0; q < 8; q++) d_[q] = s_[q];
    }
    // stage W1 rows 129..144 + row 128 (overlay in sB2)
    for (int i = tid; i < 17 * 32; i += 256) {
        int k = i >> 5, cg = i & 31;
        int srcrow = (k == 16) ? 128 : (129 + k);
        *(float4*)(s_w1 + k * HD + cg * 4) = *(const float4*)(w1 + srcrow * HD + cg * 4);
    }
    if (tid < 128) {
        s_bias[tid]       = b2[tid];
        s_bias[128 + tid] = cb1[tid];
        s_bias[256 + tid] = cw2[tid];
    }
    __syncthreads();

    // edge_attr gather (overlay)
#pragma unroll
    for (int it = 0; it < 2; it++) {
        int idx = it * 256 + tid;
        int k = idx & 15, e = idx >> 4;
        int eg = e0 + e; if (eg >= E) eg = E - 1;
        float4 v = *(const float4*)(ea + ((size_t)eg * HE + k) * T);
        *(float4*)(s_ea + k * STRIDE + e * 4) = v;
    }
    if (tid < ROWS) {
        int e = tid >> 2, t = tid & 3;
        int rn = s_rown[e], cn = s_coln[e];
        float n2 = 0.f;
#pragma unroll
        for (int d = 0; d < 3; d++) {
            float v = x[((size_t)rn * 3 + d) * T + t] - x[((size_t)cn * 3 + d) * T + t];
            s_xij[e][d][t] = v;
            n2 += v * v;
        }
        s_n2[tid] = n2;
    }
    __syncthreads();

    // ---- layer 1 (FFMA2) into acc; overlay reads finish before Alo store ----
    u64 acc1[8][4];
    {
        float4 bA = *(const float4*)(b1 + 4 * tx);
        float4 bB = *(const float4*)(b1 + 64 + 4 * tx);
        float4 wA = *(const float4*)(s_w1 + 16 * HD + 4 * tx);
        float4 wB = *(const float4*)(s_w1 + 16 * HD + 64 + 4 * tx);
#pragma unroll
        for (int r = 0; r < 8; r++) {
            int row = ty * 8 + r;
            int e = row >> 2, t = row & 3;
            const float* p1 = g_p1 + ((size_t)s_rown[e] * T + t) * HD;
            const float* p2 = g_p2 + ((size_t)s_coln[e] * T + t) * HD;
            float4 a1 = *(const float4*)(p1 + 4 * tx);
            float4 c1 = *(const float4*)(p1 + 64 + 4 * tx);
            float4 a2 = *(const float4*)(p2 + 4 * tx);
            float4 c2 = *(const float4*)(p2 + 64 + 4 * tx);
            float n2r = s_n2[row];
            acc1[r][0] = packab(bA.x + a1.x + a2.x + n2r * wA.x,
                                bA.y + a1.y + a2.y + n2r * wA.y);
            acc1[r][1] = packab(bA.z + a1.z + a2.z + n2r * wA.z,
                                bA.w + a1.w + a2.w + n2r * wA.w);
            acc1[r][2] = packab(bB.x + c1.x + c2.x + n2r * wB.x,
                                bB.y + c1.y + c2.y + n2r * wB.y);
            acc1[r][3] = packab(bB.z + c1.z + c2.z + n2r * wB.z,
                                bB.w + c1.w + c2.w + n2r * wB.w);
        }
        const float* ap = s_ea + ty * 8;
#pragma unroll
        for (int k = 0; k < HE; k++) {
            float4 a0 = *(const float4*)(ap);
            float4 a1 = *(const float4*)(ap + 4);
            ap += STRIDE;
            ulonglong2 wp0 = *(const ulonglong2*)(s_w1 + k * HD + 4 * tx);
            ulonglong2 wp1 = *(const ulonglong2*)(s_w1 + k * HD + 64 + 4 * tx);
            float av[8] = {a0.x, a0.y, a0.z, a0.w, a1.x, a1.y, a1.z, a1.w};
#pragma unroll
            for (int r = 0; r < 8; r++) {
                u64 ar = pack2(av[r]);
                FMA2(acc1[r][0], ar, wp0.x);
                FMA2(acc1[r][1], ar, wp0.y);
                FMA2(acc1[r][2], ar, wp1.x);
                FMA2(acc1[r][3], ar, wp1.y);
            }
        }
    }
    __syncthreads();   // overlay (s_ea/s_w1 in sB2) reads done before Alo store

    // ---- silu + split: Ahi -> sAhi, Alo -> sB2 ----
#pragma unroll
    for (int r = 0; r < 8; r++) {
        int row = ty * 8 + r;
#pragma unroll
        for (int cp = 0; cp < 4; cp++) {
            float lo, hi; unpack2(acc1[r][cp], lo, hi);
            lo = silu_f(lo); hi = silu_f(hi);
            int col = (cp < 2) ? (4 * tx + 2 * cp) : (64 + 4 * tx + 2 * (cp - 2));
            u32 hh, ll;
            split2(lo, hi, hh, ll);
            *(u32*)(sAhi + row * BROW + col * 2) = hh;
            *(u32*)(sB2  + row * BROW + col * 2) = ll;
        }
    }
    __syncthreads();

    // ldmatrix per-thread offsets
    const u32 aoff = (u32)((wid * 16 + (t5 & 15)) * BROW + ((t5 & 16) ? 16 : 0));
    const u32 boff = (u32)(((t5 & 7) + ((t5 >> 4) << 3)) * BROW + ((t5 & 8) << 1));

    // ---- extract Alo fragments to registers (warp-local) ----
    u32 alo[8][4];
#pragma unroll
    for (int ks = 0; ks < 8; ks++)
        LDMX4(alo[ks][0], alo[ks][1], alo[ks][2], alo[ks][3], sB2_b + aoff + ks * 32);
    __syncthreads();

    // ---- stage Blo = W2lo into sB2 ----
    {
        int row_ = tid >> 1, half_ = tid & 1;
        const float4* s_ = (const float4*)((const char*)g_w2lo + row_ * 256 + half_ * 128);
        float4* d_ = (float4*)(sB2 + row_ * BROW + half_ * 128);
#pragma unroll
        for (int q = 0; q < 8; q++) d_[q] = s_[q];
    }
    __syncthreads();

    float d[16][4];
#pragma unroll
    for (int n = 0; n < 16; n++)
#pragma unroll
        for (int q = 0; q < 4; q++) d[n][q] = 0.f;

    // ---- GEMM1 single pass: Ahi*Bhi + Alo*Bhi + Ahi*Blo ----
#pragma unroll 1
    for (int ks = 0; ks < 8; ks++) {
        u32 ah[4];
        LDMX4(ah[0], ah[1], ah[2], ah[3], sAhi_b + aoff + ks * 32);
#pragma unroll
        for (int j = 0; j < 8; j++) {
            u32 bh0, bh1, bh2, bh3, bl0, bl1, bl2, bl3;
            LDMX4(bh0, bh1, bh2, bh3, sBhi_b + boff + j * (16 * BROW) + ks * 32);
            LDMX4(bl0, bl1, bl2, bl3, sB2_b  + boff + j * (16 * BROW) + ks * 32);
            MMA16816(d[2 * j],     ah[0], ah[1], ah[2], ah[3], bh0, bh1);
            MMA16816(d[2 * j + 1], ah[0], ah[1], ah[2], ah[3], bh2, bh3);
            MMA16816(d[2 * j],     alo[ks][0], alo[ks][1], alo[ks][2], alo[ks][3], bh0, bh1);
            MMA16816(d[2 * j + 1], alo[ks][0], alo[ks][1], alo[ks][2], alo[ks][3], bh2, bh3);
            MMA16816(d[2 * j],     ah[0], ah[1], ah[2], ah[3], bl0, bl1);
            MMA16816(d[2 * j + 1], ah[0], ah[1], ah[2], ah[3], bl2, bl3);
        }
    }
    __syncthreads();   // all B/A reads done before restage

    // ---- readback GEMM1: +b2, silu, scatter m_i, A2hi->sAhi, A2lo->regs ----
    const int g = t5 >> 2, tg = t5 & 3;
    const int rowA = wid * 16 + g, rowB = rowA + 8;
    const int eA = rowA >> 2, tA = rowA & 3;
    const int eB = rowB >> 2, tB = rowB & 3;
    const bool okA = (e0 + eA) < E, okB = (e0 + eB) < E;
    float* mA = g_mi + ((size_t)s_rown[eA] * T + tA) * HD;
    float* mB = g_mi + ((size_t)s_rown[eB] * T + tB) * HD;

#pragma unroll
    for (int n = 0; n < 16; n++) {
        int c = 8 * n + 2 * tg;
        float v0 = silu_f(d[n][0] + s_bias[c]);
        float v1 = silu_f(d[n][1] + s_bias[c + 1]);
        float v2 = silu_f(d[n][2] + s_bias[c]);
        float v3 = silu_f(d[n][3] + s_bias[c + 1]);
        if (okA) REDV2(mA + c, v0, v1);
        if (okB) REDV2(mB + c, v2, v3);
        int ks = n >> 1, p = n & 1;
        u32 hh, ll;
        split2(v0, v1, hh, ll);
        *(u32*)(sAhi + rowA * BROW + c * 2) = hh;
        alo[ks][2 * p] = ll;
        split2(v2, v3, hh, ll);
        *(u32*)(sAhi + rowB * BROW + c * 2) = hh;
        alo[ks][2 * p + 1] = ll;
        d[n][0] = d[n][1] = d[n][2] = d[n][3] = 0.f;
    }

    // ---- restage B: CW1hi -> sBhi, CW1lo -> sB2 ----
    __syncthreads();
    {
        int row_ = tid >> 1, half_ = tid & 1;
        const float4* sh = (const float4*)((const char*)g_c1hi + row_ * 256 + half_ * 128);
        const float4* sl = (const float4*)((const char*)g_c1lo + row_ * 256 + half_ * 128);
        float4* dh = (float4*)(sBhi + row_ * BROW + half_ * 128);
        float4* dl = (float4*)(sB2  + row_ * BROW + half_ * 128);
#pragma unroll
        for (int q = 0; q < 8; q++) { dh[q] = sh[q]; dl[q] = sl[q]; }
    }
    __syncthreads();

    // ---- GEMM2 single pass: A2hi*Bhi + A2lo*Bhi + A2hi*Blo ----
#pragma unroll 1
    for (int ks = 0; ks < 8; ks++) {
        u32 ah[4];
        LDMX4(ah[0], ah[1], ah[2], ah[3], sAhi_b + aoff + ks * 32);
#pragma unroll
        for (int j = 0; j < 8; j++) {
            u32 bh0, bh1, bh2, bh3, bl0, bl1, bl2, bl3;
            LDMX4(bh0, bh1, bh2, bh3, sBhi_b + boff + j * (16 * BROW) + ks * 32);
            LDMX4(bl0, bl1, bl2, bl3, sB2_b  + boff + j * (16 * BROW) + ks * 32);
            MMA16816(d[2 * j],     ah[0], ah[1], ah[2], ah[3], bh0, bh1);
            MMA16816(d[2 * j + 1], ah[0], ah[1], ah[2], ah[3], bh2, bh3);
            MMA16816(d[2 * j],     alo[ks][0], alo[ks][1], alo[ks][2], alo[ks][3], bh0, bh1);
            MMA16816(d[2 * j + 1], alo[ks][0], alo[ks][1], alo[ks][2], alo[ks][3], bh2, bh3);
            MMA16816(d[2 * j],     ah[0], ah[1], ah[2], ah[3], bl0, bl1);
            MMA16816(d[2 * j + 1], ah[0], ah[1], ah[2], ah[3], bl2, bl3);
        }
    }

    // ---- readback GEMM2: silu, dot cw2, quad-reduce, coord epilogue ----
    {
        float pA = 0.f, pB = 0.f;
#pragma unroll
        for (int n = 0; n < 16; n++) {
            int c = 8 * n + 2 * tg;
            pA += silu_f(d[n][0] + s_bias[128 + c])     * s_bias[256 + c];
            pA += silu_f(d[n][1] + s_bias[128 + c + 1]) * s_bias[256 + c + 1];
            pB += silu_f(d[n][2] + s_bias[128 + c])     * s_bias[256 + c];
            pB += silu_f(d[n][3] + s_bias[128 + c + 1]) * s_bias[256 + c + 1];
        }
        pA += __shfl_xor_sync(0xffffffffu, pA, 1);
        pA += __shfl_xor_sync(0xffffffffu, pA, 2);
        pB += __shfl_xor_sync(0xffffffffu, pB, 1);
        pB += __shfl_xor_sync(0xffffffffu, pB, 2);
        if (tg == 0) {
            float cb2v = cb2[0];
#pragma unroll
            for (int half = 0; half < 2; half++) {
                int row = half ? rowB : rowA;
                float p = half ? pB : pA;
                int e = row >> 2, t = row & 3;
                if (e0 + e < E) {
                    float cval = (p + cb2v) *
                        __fdividef(1.0f, sqrtf(s_n2[row] + EPSF) + 1.0f);
                    int node = s_rown[e];
#pragma unroll
                    for (int dd = 0; dd < 3; dd++)
                        atomicAdd(&g_agg[((size_t)node * 3 + dd) * T + t],
                                  cval * s_xij[e][dd][t]);
                    if (t == 0) atomicAdd(&g_cnt[node], 1.0f);
                }
            }
        }
    }
}

// ---------------- node kernel ([N,T,HD] g_mi gather) ----------------
__global__ __launch_bounds__(256, 2) void node_kernel(
    const float* __restrict__ x, const float* __restrict__ h,
    const float* __restrict__ nw1, const float* __restrict__ nb1,
    const float* __restrict__ nw2, const float* __restrict__ nb2,
    float* __restrict__ out_x, float* __restrict__ out_h, int N)
{
    extern __shared__ float sm[];
    float* s_buf = sm;
    float* s_w   = sm + HD * STRIDE;

    const int tid = threadIdx.x, tx = tid & 15, ty = tid >> 4;
    const int n0 = blockIdx.x * NPB;

#pragma unroll
    for (int it = 0; it < 2; it++) {
        int idx = it * 256 + tid;
        if (idx < NPB * 12) {
            int n = n0 + idx / 12;
            if (n < N) {
                int rem = idx % 12, d = rem >> 2, t = rem & 3;
                float cv = fmaxf(g_cnt[n], 1.0f);
                int off = (n * 3 + d) * T + t;
                out_x[off] = x[off] + g_agg[off] * __fdividef(1.0f, cv);
            }
        }
    }

#pragma unroll
    for (int it = 0; it < 8; it++) {
        int idx = it * 256 + tid;
        int k = idx & 63, nl = idx >> 6;
        int node = n0 + nl; if (node >= N) node = N - 1;
        float4 v = *(const float4*)(h + ((size_t)node * HH + k) * T);
        *(float4*)(s_buf + k * STRIDE + nl * 4) = v;
    }
#pragma unroll
    for (int it = 0; it < 8; it++) {
        int idx = it * 256 + tid;
        int kq = idx & 15, t = (idx >> 4) & 3, nl = idx >> 6;
        int node = n0 + nl; if (node >= N) node = N - 1;
        float4 v = *(const float4*)(g_mi + ((size_t)node * T + t) * HD + kq * 4);
        s_buf[(HH + kq * 4 + 0) * STRIDE + nl * 4 + t] = v.x;
        s_buf[(HH + kq * 4 + 1) * STRIDE + nl * 4 + t] = v.y;
        s_buf[(HH + kq * 4 + 2) * STRIDE + nl * 4 + t] = v.z;
        s_buf[(HH + kq * 4 + 3) * STRIDE + nl * 4 + t] = v.w;
    }

    u64 acc[8][4];
    {
        float4 bA = *(const float4*)(nb1 + 4 * tx);
        float4 bB = *(const float4*)(nb1 + 64 + 4 * tx);
        u64 i0 = packab(bA.x, bA.y), i1 = packab(bA.z, bA.w);
        u64 i2 = packab(bB.x, bB.y), i3 = packab(bB.z, bB.w);
#pragma unroll
        for (int r = 0; r < 8; r++) {
            acc[r][0] = i0; acc[r][1] = i1; acc[r][2] = i2; acc[r][3] = i3;
        }
    }
    float4 pre[4];
#pragma unroll
    for (int i = 0; i < 4; i++) {
        int off = i * 1024 + tid * 4;
        pre[i] = *(const float4*)(nw1 + (off >> 7) * HD + (off & 127));
    }
#pragma unroll 1
    for (int kc = 0; kc < 4; kc++) {
        __syncthreads();
#pragma unroll
        for (int i = 0; i < 4; i++)
            *(float4*)(s_w + i * 1024 + tid * 4) = pre[i];
        __syncthreads();
        {
            int kbase = (kc + 1) * 32;
            if (kbase < 192) {
#pragma unroll
                for (int i = 0; i < 4; i++) {
                    int off = i * 1024 + tid * 4;
                    pre[i] = *(const float4*)(nw1 + (kbase + (off >> 7)) * HD + (off & 127));
                }
            }
        }
        const float* ap = s_buf + (kc * 32) * STRIDE + ty * 8;
#pragma unroll 8
        for (int kk = 0; kk < 32; kk++) {
            float4 a0 = *(const float4*)(ap);
            float4 a1 = *(const float4*)(ap + 4);
            ap += STRIDE;
            ulonglong2 bA = *(const ulonglong2*)(s_w + kk * HD + 4 * tx);
            ulonglong2 bB = *(const ulonglong2*)(s_w + kk * HD + 64 + 4 * tx);
            float av[8] = {a0.x, a0.y, a0.z, a0.w, a1.x, a1.y, a1.z, a1.w};
#pragma unroll
            for (int r = 0; r < 8; r++) {
                u64 ar = pack2(av[r]);
                FMA2(acc[r][0], ar, bA.x);
                FMA2(acc[r][1], ar, bA.y);
                FMA2(acc[r][2], ar, bB.x);
                FMA2(acc[r][3], ar, bB.y);
            }
        }
    }
    __syncthreads();

#pragma unroll
    for (int it = 0; it < 8; it++) {
        int idx = it * 256 + tid;
        int kq = idx & 15, t = (idx >> 4) & 3, nl = idx >> 6;
        int node = n0 + nl; if (node >= N) node = N - 1;
        float4 v = *(const float4*)(g_mi + ((size_t)node * T + t) * HD + 64 + kq * 4);
        s_buf[(kq * 4 + 0) * STRIDE + nl * 4 + t] = v.x;
        s_buf[(kq * 4 + 1) * STRIDE + nl * 4 + t] = v.y;
        s_buf[(kq * 4 + 2) * STRIDE + nl * 4 + t] = v.z;
        s_buf[(kq * 4 + 3) * STRIDE + nl * 4 + t] = v.w;
    }
#pragma unroll 1
    for (int kc = 0; kc < 2; kc++) {
        __syncthreads();
#pragma unroll
        for (int i = 0; i < 4; i++)
            *(float4*)(s_w + i * 1024 + tid * 4) = pre[i];
        __syncthreads();
        if (kc == 0) {
#pragma unroll
            for (int i = 0; i < 4; i++) {
                int off = i * 1024 + tid * 4;
                pre[i] = *(const float4*)(nw1 + (160 + (off >> 7)) * HD + (off & 127));
            }
        }
        const float* ap = s_buf + (kc * 32) * STRIDE + ty * 8;
#pragma unroll 8
        for (int kk = 0; kk < 32; kk++) {
            float4 a0 = *(const float4*)(ap);
            float4 a1 = *(const float4*)(ap + 4);
            ap += STRIDE;
            ulonglong2 bA = *(const ulonglong2*)(s_w + kk * HD + 4 * tx);
            ulonglong2 bB = *(const ulonglong2*)(s_w + kk * HD + 64 + 4 * tx);
            float av[8] = {a0.x, a0.y, a0.z, a0.w, a1.x, a1.y, a1.z, a1.w};
#pragma unroll
            for (int r = 0; r < 8; r++) {
                u64 ar = pack2(av[r]);
                FMA2(acc[r][0], ar, bA.x);
                FMA2(acc[r][1], ar, bA.y);
                FMA2(acc[r][2], ar, bB.x);
                FMA2(acc[r][3], ar, bB.y);
            }
        }
    }

    float o1[8][8];
#pragma unroll
    for (int r = 0; r < 8; r++)
#pragma unroll
        for (int cp = 0; cp < 4; cp++) {
            float lo, hi; unpack2(acc[r][cp], lo, hi);
            o1[r][2 * cp]     = silu_f(lo);
            o1[r][2 * cp + 1] = silu_f(hi);
        }
    __syncthreads();
#pragma unroll
    for (int c = 0; c < 8; c++) {
        int col = (c < 4) ? 4 * tx + c : 60 + 4 * tx + c;
        *(float4*)(s_buf + col * STRIDE + ty * 8) =
            make_float4(o1[0][c], o1[1][c], o1[2][c], o1[3][c]);
        *(float4*)(s_buf + col * STRIDE + ty * 8 + 4) =
            make_float4(o1[4][c], o1[5][c], o1[6][c], o1[7][c]);
    }

    u64 acc2[8][2];
    {
        float4 b = *(const float4*)(nb2 + 4 * tx);
        u64 i0 = packab(b.x, b.y), i1 = packab(b.z, b.w);
#pragma unroll
        for (int r = 0; r < 8; r++) { acc2[r][0] = i0; acc2[r][1] = i1; }
    }
    float4 pre2[2];
#pragma unroll
    for (int i = 0; i < 2; i++) {
        int off = i * 1024 + tid * 4;
        pre2[i] = *(const float4*)(nw2 + (off >> 6) * HH + (off & 63));
    }
#pragma unroll 1
    for (int kc = 0; kc < 4; kc++) {
        __syncthreads();
#pragma unroll
        for (int i = 0; i < 2; i++)
            *(float4*)(s_w + i * 1024 + tid * 4) = pre2[i];
        __syncthreads();
        if (kc < 3) {
#pragma unroll
            for (int i = 0; i < 2; i++) {
                int off = i * 1024 + tid * 4;
                pre2[i] = *(const float4*)(nw2 + ((kc + 1) * 32 + (off >> 6)) * HH + (off & 63));
            }
        }
        const float* ap = s_buf + (kc * 32) * STRIDE + ty * 8;
#pragma unroll 8
        for (int kk = 0; kk < 32; kk++) {
            float4 a0 = *(const float4*)(ap);
            float4 a1 = *(const float4*)(ap + 4);
            ap += STRIDE;
            ulonglong2 w01 = *(const ulonglong2*)(s_w + kk * HH + 4 * tx);
            float av[8] = {a0.x, a0.y, a0.z, a0.w, a1.x, a1.y, a1.z, a1.w};
#pragma unroll
            for (int r = 0; r < 8; r++) {
                u64 ar = pack2(av[r]);
                FMA2(acc2[r][0], ar, w01.x);
                FMA2(acc2[r][1], ar, w01.y);
            }
        }
    }
    float o2[8][4];
#pragma unroll
    for (int r = 0; r < 8; r++) {
        unpack2(acc2[r][0], o2[r][0], o2[r][1]);
        unpack2(acc2[r][1], o2[r][2], o2[r][3]);
    }
#pragma unroll
    for (int half = 0; half < 2; half++) {
        int n = n0 + 2 * ty + half;
        if (n < N) {
#pragma unroll
            for (int c = 0; c < 4; c++) {
                int col = 4 * tx + c;
                *(float4*)(out_h + ((size_t)n * HH + col) * T) =
                    make_float4(o2[half * 4 + 0][c], o2[half * 4 + 1][c],
                                o2[half * 4 + 2][c], o2[half * 4 + 3][c]);
            }
        }
    }
}

extern "C" void kernel_launch(void* const* d_in, const int* in_sizes, int n_in,
                              void* d_out, int out_size)
{
    const float* x   = (const float*)d_in[0];
    const float* h   = (const float*)d_in[1];
    const int*   ei  = (const int*)  d_in[2];
    const float* ea  = (const float*)d_in[3];
    const float* ew1 = (const float*)d_in[5];
    const float* eb1 = (const float*)d_in[6];
    const float* ew2 = (const float*)d_in[7];
    const float* eb2 = (const float*)d_in[8];
    const float* cw1 = (const float*)d_in[9];
    const float* cb1 = (const float*)d_in[10];
    const float* cw2 = (const float*)d_in[11];
    const float* cb2 = (const float*)d_in[12];
    const float* nw1 = (const float*)d_in[13];
    const float* nb1 = (const float*)d_in[14];
    const float* nw2 = (const float*)d_in[15];
    const float* nb2 = (const float*)d_in[16];

    int N = in_sizes[0] / (3 * T);
    int E = in_sizes[3] / (HE * T);

    float* out_x = (float*)d_out;
    float* out_h = out_x + (size_t)N * 3 * T;

    const int pre_smem  = (HH * STRIDE + 32 * HD) * sizeof(float);
    const int node_smem = (HD * STRIDE + 32 * HD) * sizeof(float);
    const int edge_smem = 105984;
    cudaFuncSetAttribute(pre_kernel,  cudaFuncAttributeMaxDynamicSharedMemorySize, pre_smem);
    cudaFuncSetAttribute(node_kernel, cudaFuncAttributeMaxDynamicSharedMemorySize, node_smem);
    cudaFuncSetAttribute(edge_kernel, cudaFuncAttributeMaxDynamicSharedMemorySize, edge_smem);

    zero_kernel<<<2048, 256>>>(N);
    wimg_kernel<<<(HD * HD) / 256, 256>>>(ew2, cw1);
    pre_kernel<<<(N + NPRE - 1) / NPRE, 256, pre_smem>>>(h, ew1, N);
    edge_kernel<<<(E + EPB - 1) / EPB, 256, edge_smem>>>(
        x, ei, ea, ew1, eb1, eb2, cb1, cw2, cb2, E);
    node_kernel<<<(N + NPB - 1) / NPB, 256, node_smem>>>(
        x, h, nw1, nb1, nw2, nb2, out_x, out_h, N);
}

// round 17
// speedup vs baseline: 1.2431x; 1.0612x over previous
#include <cuda_runtime.h>
#include <cuda_bf16.h>
#include <cstdint>

#define T    4
#define HH   64
#define HE   16
#define HD   128
#define EPB  32
#define ROWS 128
#define STRIDE 132
#define NPRE 32
#define NPB  32
#define MAXN 20000
#define EPSF 1e-8f
#define BROW 272          // bf16 operand row stride in bytes (136 bf16)

typedef unsigned long long u64;
typedef unsigned int u32;

// ---------------- device globals ----------------
__device__ float g_mi[MAXN * T * HD];          // [N, T, HD]
__device__ float g_agg[MAXN * 3 * T];
__device__ float g_cnt[MAXN];
__device__ float g_p1[(size_t)MAXN * T * HD];
__device__ float g_p2[(size_t)MAXN * T * HD];
__device__ float g_zerobias[HD];
// plain [n][k] bf16 hi/lo images of W2^T and CW1^T
__device__ __nv_bfloat16 g_w2hi[HD * HD], g_w2lo[HD * HD];
__device__ __nv_bfloat16 g_c1hi[HD * HD], g_c1lo[HD * HD];

__device__ __forceinline__ float silu_f(float v) {
    return v * __fdividef(1.0f, 1.0f + __expf(-v));
}

#define FMA2(d, a, b) asm("fma.rn.f32x2 %0, %1, %2, %0;" : "+l"(d) : "l"(a), "l"(b))
__device__ __forceinline__ u64 packab(float a, float b) {
    u64 r; asm("mov.b64 %0, {%1, %2};" : "=l"(r) : "f"(a), "f"(b)); return r;
}
__device__ __forceinline__ u64 pack2(float v) { return packab(v, v); }
__device__ __forceinline__ void unpack2(u64 v, float& lo, float& hi) {
    asm("mov.b64 {%0, %1}, %2;" : "=f"(lo), "=f"(hi) : "l"(v));
}
__device__ __forceinline__ u32 smem_u32(const void* p) {
    u32 a;
    asm("{ .reg .u64 t; cvta.to.shared.u64 t, %1; cvt.u32.u64 %0, t; }"
        : "=r"(a) : "l"(p));
    return a;
}
__device__ __forceinline__ void split2(float a, float b, u32& h, u32& l) {
    __nv_bfloat162 hp, lp;
    hp.x = __float2bfloat16(a); hp.y = __float2bfloat16(b);
    lp.x = __float2bfloat16(a - __bfloat162float(hp.x));
    lp.y = __float2bfloat16(b - __bfloat162float(hp.y));
    h = *reinterpret_cast<u32*>(&hp);
    l = *reinterpret_cast<u32*>(&lp);
}

#define LDMX4(r0, r1, r2, r3, addr) \
    asm volatile("ldmatrix.sync.aligned.m8n8.x4.shared.b16 {%0,%1,%2,%3}, [%4];" \
        : "=r"(r0), "=r"(r1), "=r"(r2), "=r"(r3) : "r"(addr))

#define MMA16816(d, a0, a1, a2, a3, b0, b1) \
    asm volatile("mma.sync.aligned.m16n8k16.row.col.f32.bf16.bf16.f32 " \
        "{%0,%1,%2,%3}, {%4,%5,%6,%7}, {%8,%9}, {%0,%1,%2,%3};" \
        : "+f"((d)[0]), "+f"((d)[1]), "+f"((d)[2]), "+f"((d)[3]) \
        : "r"(a0), "r"(a1), "r"(a2), "r"(a3), "r"(b0), "r"(b1))

#define REDV2(p, v0, v1) \
    asm volatile("red.global.add.v2.f32 [%0], {%1,%2};" \
                 :: "l"(p), "f"(v0), "f"(v1) : "memory")

#define CPASYNC16(dst, src) \
    asm volatile("cp.async.cg.shared.global [%0], [%1], 16;" \
                 :: "r"(dst), "l"(src) : "memory")
#define CPCOMMIT() asm volatile("cp.async.commit_group;" ::: "memory")
#define CPWAIT0()  asm volatile("cp.async.wait_group 0;" ::: "memory")

// ---------------- small kernels ----------------
__global__ void zero_kernel(int n) {
    int stride = gridDim.x * blockDim.x;
    int base = blockIdx.x * blockDim.x + threadIdx.x;
    for (int i = base; i < n * HD * T; i += stride) g_mi[i] = 0.0f;
    for (int i = base; i < n * 3 * T;  i += stride) g_agg[i] = 0.0f;
    for (int i = base; i < n;          i += stride) g_cnt[i] = 0.0f;
}

__global__ void wimg_kernel(const float* __restrict__ w2, const float* __restrict__ cw1) {
    int idx = blockIdx.x * 256 + threadIdx.x;   // 16384
    int n = idx >> 7, k = idx & 127;
    float v2 = w2[k * HD + n];
    __nv_bfloat16 h2 = __float2bfloat16(v2);
    g_w2hi[idx] = h2;
    g_w2lo[idx] = __float2bfloat16(v2 - __bfloat162float(h2));
    float v3 = cw1[k * HD + n];
    __nv_bfloat16 h3 = __float2bfloat16(v3);
    g_c1hi[idx] = h3;
    g_c1lo[idx] = __float2bfloat16(v3 - __bfloat162float(h3));
}

// ---------------- FFMA2 GEMM tile (pre/node kernels) ----------------
template<int NCHUNK, int KLIM, bool ACT>
__device__ __forceinline__ void gemm_phase(
    const float* __restrict__ sA, float* __restrict__ sW,
    const float* __restrict__ gW, const float* __restrict__ gB,
    int tid, int tx, int ty, float (&out)[8][8])
{
    u64 acc[8][4];
    {
        float4 bA = *(const float4*)(gB + 4 * tx);
        float4 bB = *(const float4*)(gB + 64 + 4 * tx);
        u64 i0 = packab(bA.x, bA.y), i1 = packab(bA.z, bA.w);
        u64 i2 = packab(bB.x, bB.y), i3 = packab(bB.z, bB.w);
#pragma unroll
        for (int r = 0; r < 8; r++) {
            acc[r][0] = i0; acc[r][1] = i1; acc[r][2] = i2; acc[r][3] = i3;
        }
    }
    float4 pre[4];
#pragma unroll
    for (int i = 0; i < 4; i++) {
        int off = i * 1024 + tid * 4;
        int kg = off >> 7;
        pre[i] = (kg < KLIM) ? *(const float4*)(gW + kg * HD + (off & 127))
                             : make_float4(0.f, 0.f, 0.f, 0.f);
    }
#pragma unroll 1
    for (int kc = 0; kc < NCHUNK; kc++) {
        __syncthreads();
#pragma unroll
        for (int i = 0; i < 4; i++)
            *(float4*)(sW + i * 1024 + tid * 4) = pre[i];
        __syncthreads();
        if (kc + 1 < NCHUNK) {
#pragma unroll
            for (int i = 0; i < 4; i++) {
                int off = i * 1024 + tid * 4;
                int kg = (kc + 1) * 32 + (off >> 7);
                pre[i] = (kg < KLIM) ? *(const float4*)(gW + kg * HD + (off & 127))
                                     : make_float4(0.f, 0.f, 0.f, 0.f);
            }
        }
        const float* ap = sA + (kc * 32) * STRIDE + ty * 8;
#pragma unroll 8
        for (int kk = 0; kk < 32; kk++) {
            float4 a0 = *(const float4*)(ap);
            float4 a1 = *(const float4*)(ap + 4);
            ap += STRIDE;
            ulonglong2 bA = *(const ulonglong2*)(sW + kk * HD + 4 * tx);
            ulonglong2 bB = *(const ulonglong2*)(sW + kk * HD + 64 + 4 * tx);
            float av[8] = {a0.x, a0.y, a0.z, a0.w, a1.x, a1.y, a1.z, a1.w};
#pragma unroll
            for (int r = 0; r < 8; r++) {
                u64 ar = pack2(av[r]);
                FMA2(acc[r][0], ar, bA.x);
                FMA2(acc[r][1], ar, bA.y);
                FMA2(acc[r][2], ar, bB.x);
                FMA2(acc[r][3], ar, bB.y);
            }
        }
    }
#pragma unroll
    for (int r = 0; r < 8; r++)
#pragma unroll
        for (int cp = 0; cp < 4; cp++) {
            float lo, hi; unpack2(acc[r][cp], lo, hi);
            out[r][cp * 2]     = ACT ? silu_f(lo) : lo;
            out[r][cp * 2 + 1] = ACT ? silu_f(hi) : hi;
        }
}

// ---------------- P1/P2 precompute ----------------
__global__ __launch_bounds__(256, 2) void pre_kernel(
    const float* __restrict__ h, const float* __restrict__ w1, int N)
{
    extern __shared__ float sm[];
    float* s_h = sm;
    float* s_w = sm + HH * STRIDE;
    const int tid = threadIdx.x, tx = tid & 15, ty = tid >> 4;
    const int n0 = blockIdx.x * NPRE;
#pragma unroll
    for (int it = 0; it < 8; it++) {
        int idx = it * 256 + tid;
        int k = idx & 63, nl = idx >> 6;
        int node = n0 + nl; if (node >= N) node = N - 1;
        float4 v = *(const float4*)(h + ((size_t)node * HH + k) * T);
        *(float4*)(s_h + k * STRIDE + nl * 4) = v;
    }
    float o[8][8];
    gemm_phase<2, HH, false>(s_h, s_w, w1, g_zerobias, tid, tx, ty, o);
#pragma unroll
    for (int r = 0; r < 8; r++) {
        int row = ty * 8 + r;
        int node = n0 + (row >> 2), t = row & 3;
        if (node < N) {
            float* p = g_p1 + ((size_t)node * T + t) * HD;
            *(float4*)(p + 4 * tx)      = make_float4(o[r][0], o[r][1], o[r][2], o[r][3]);
            *(float4*)(p + 64 + 4 * tx) = make_float4(o[r][4], o[r][5], o[r][6], o[r][7]);
        }
    }
    gemm_phase<2, HH, false>(s_h, s_w, w1 + HH * HD, g_zerobias, tid, tx, ty, o);
#pragma unroll
    for (int r = 0; r < 8; r++) {
        int row = ty * 8 + r;
        int node = n0 + (row >> 2), t = row & 3;
        if (node < N) {
            float* p = g_p2 + ((size_t)node * T + t) * HD;
            *(float4*)(p + 4 * tx)      = make_float4(o[r][0], o[r][1], o[r][2], o[r][3]);
            *(float4*)(p + 64 + 4 * tx) = make_float4(o[r][4], o[r][5], o[r][6], o[r][7]);
        }
    }
}

// ---------------- edge kernel: cp.async-pipelined split-bf16 HMMA ----------------
__global__ __launch_bounds__(256, 2) void edge_kernel(
    const float* __restrict__ x,
    const int* __restrict__ ei, const float* __restrict__ ea,
    const float* __restrict__ w1, const float* __restrict__ b1,
    const float* __restrict__ b2, const float* __restrict__ cb1,
    const float* __restrict__ cw2, const float* __restrict__ cb2,
    int E)
{
    extern __shared__ __align__(16) char smc[];
    char* sAhi = smc;                        // 34816
    char* sBhi = smc + 34816;                // 34816
    char* sB2  = smc + 69632;                // 34816 (Alo, then Blo)
    float* s_ea   = (float*)(smc + 69632);           // overlay in sB2
    float* s_w1   = (float*)(smc + 69632 + 8448);    // overlay in sB2
    float* s_bias = (float*)(smc + 104448);          // 384 floats

    __shared__ int   s_rown[EPB], s_coln[EPB];
    __shared__ float s_xij[EPB][3][T];
    __shared__ float s_n2[ROWS];

    const int tid = threadIdx.x, tx = tid & 15, ty = tid >> 4;
    const int wid = tid >> 5, t5 = tid & 31;
    const int e0 = blockIdx.x * EPB;

    const u32 sAhi_b = smem_u32(sAhi), sBhi_b = smem_u32(sBhi);
    const u32 sB2_b = smem_u32(sB2);

    // per-thread staging coords (copy 128x256B image -> 272B-stride buffer)
    const int srow = tid >> 1, shalf = tid & 1;
    const int ssrc = srow * 256 + shalf * 128;
    const u32 sdstB2  = sB2_b  + (u32)(srow * BROW + shalf * 128);
    const u32 sdstBhi = sBhi_b + (u32)(srow * BROW + shalf * 128);

    if (tid < EPB) {
        int eg = e0 + tid; if (eg >= E) eg = E - 1;
        s_rown[tid] = ei[eg];
        s_coln[tid] = ei[E + eg];
    }
    // stage Bhi = W2hi early (own buffer; overlaps later gathers)
    {
        const float4* s_ = (const float4*)((const char*)g_w2hi + ssrc);
        float4* d_ = (float4*)(sBhi + srow * BROW + shalf * 128);
#pragma unroll
        for (int q = 0; q < 8; q++) d_[q] = s_[q];
    }
    // stage W1 rows 129..144 + row 128 (overlay in sB2)
    for (int i = tid; i < 17 * 32; i += 256) {
        int k = i >> 5, cg = i & 31;
        int srcrow = (k == 16) ? 128 : (129 + k);
        *(float4*)(s_w1 + k * HD + cg * 4) = *(const float4*)(w1 + srcrow * HD + cg * 4);
    }
    if (tid < 128) {
        s_bias[tid]       = b2[tid];
        s_bias[128 + tid] = cb1[tid];
        s_bias[256 + tid] = cw2[tid];
    }
    __syncthreads();

    // edge_attr gather (overlay)
#pragma unroll
    for (int it = 0; it < 2; it++) {
        int idx = it * 256 + tid;
        int k = idx & 15, e = idx >> 4;
        int eg = e0 + e; if (eg >= E) eg = E - 1;
        float4 v = *(const float4*)(ea + ((size_t)eg * HE + k) * T);
        *(float4*)(s_ea + k * STRIDE + e * 4) = v;
    }
    if (tid < ROWS) {
        int e = tid >> 2, t = tid & 3;
        int rn = s_rown[e], cn = s_coln[e];
        float n2 = 0.f;
#pragma unroll
        for (int d = 0; d < 3; d++) {
            float v = x[((size_t)rn * 3 + d) * T + t] - x[((size_t)cn * 3 + d) * T + t];
            s_xij[e][d][t] = v;
            n2 += v * v;
        }
        s_n2[tid] = n2;
    }
    __syncthreads();

    // ---- layer 1 (FFMA2) ----
    u64 acc1[8][4];
    {
        float4 bA = *(const float4*)(b1 + 4 * tx);
        float4 bB = *(const float4*)(b1 + 64 + 4 * tx);
        float4 wA = *(const float4*)(s_w1 + 16 * HD + 4 * tx);
        float4 wB = *(const float4*)(s_w1 + 16 * HD + 64 + 4 * tx);
#pragma unroll
        for (int r = 0; r < 8; r++) {
            int row = ty * 8 + r;
            int e = row >> 2, t = row & 3;
            const float* p1 = g_p1 + ((size_t)s_rown[e] * T + t) * HD;
            const float* p2 = g_p2 + ((size_t)s_coln[e] * T + t) * HD;
            float4 a1 = *(const float4*)(p1 + 4 * tx);
            float4 c1 = *(const float4*)(p1 + 64 + 4 * tx);
            float4 a2 = *(const float4*)(p2 + 4 * tx);
            float4 c2 = *(const float4*)(p2 + 64 + 4 * tx);
            float n2r = s_n2[row];
            acc1[r][0] = packab(bA.x + a1.x + a2.x + n2r * wA.x,
                                bA.y + a1.y + a2.y + n2r * wA.y);
            acc1[r][1] = packab(bA.z + a1.z + a2.z + n2r * wA.z,
                                bA.w + a1.w + a2.w + n2r * wA.w);
            acc1[r][2] = packab(bB.x + c1.x + c2.x + n2r * wB.x,
                                bB.y + c1.y + c2.y + n2r * wB.y);
            acc1[r][3] = packab(bB.z + c1.z + c2.z + n2r * wB.z,
                                bB.w + c1.w + c2.w + n2r * wB.w);
        }
        const float* ap = s_ea + ty * 8;
#pragma unroll
        for (int k = 0; k < HE; k++) {
            float4 a0 = *(const float4*)(ap);
            float4 a1 = *(const float4*)(ap + 4);
            ap += STRIDE;
            ulonglong2 wp0 = *(const ulonglong2*)(s_w1 + k * HD + 4 * tx);
            ulonglong2 wp1 = *(const ulonglong2*)(s_w1 + k * HD + 64 + 4 * tx);
            float av[8] = {a0.x, a0.y, a0.z, a0.w, a1.x, a1.y, a1.z, a1.w};
#pragma unroll
            for (int r = 0; r < 8; r++) {
                u64 ar = pack2(av[r]);
                FMA2(acc1[r][0], ar, wp0.x);
                FMA2(acc1[r][1], ar, wp0.y);
                FMA2(acc1[r][2], ar, wp1.x);
                FMA2(acc1[r][3], ar, wp1.y);
            }
        }
    }
    __syncthreads();   // overlay reads done before Alo store

    // ---- silu + split: Ahi -> sAhi, Alo -> sB2 ----
#pragma unroll
    for (int r = 0; r < 8; r++) {
        int row = ty * 8 + r;
#pragma unroll
        for (int cp = 0; cp < 4; cp++) {
            float lo, hi; unpack2(acc1[r][cp], lo, hi);
            lo = silu_f(lo); hi = silu_f(hi);
            int col = (cp < 2) ? (4 * tx + 2 * cp) : (64 + 4 * tx + 2 * (cp - 2));
            u32 hh, ll;
            split2(lo, hi, hh, ll);
            *(u32*)(sAhi + row * BROW + col * 2) = hh;
            *(u32*)(sB2  + row * BROW + col * 2) = ll;
        }
    }
    __syncthreads();

    // ldmatrix per-thread offsets
    const u32 aoff = (u32)((wid * 16 + (t5 & 15)) * BROW + ((t5 & 16) ? 16 : 0));
    const u32 boff = (u32)(((t5 & 7) + ((t5 >> 4) << 3)) * BROW + ((t5 & 8) << 1));

    // ---- extract Alo fragments to registers (warp-local) ----
    u32 alo[8][4];
#pragma unroll
    for (int ks = 0; ks < 8; ks++)
        LDMX4(alo[ks][0], alo[ks][1], alo[ks][2], alo[ks][3], sB2_b + aoff + ks * 32);
    __syncthreads();

    // ---- async stage Blo = W2lo into sB2 (overlaps GEMM1 hi-pass) ----
    {
        const char* src = (const char*)g_w2lo + ssrc;
#pragma unroll
        for (int q = 0; q < 8; q++) CPASYNC16(sdstB2 + q * 16, src + q * 16);
        CPCOMMIT();
    }

    float d[16][4];
#pragma unroll
    for (int n = 0; n < 16; n++)
#pragma unroll
        for (int q = 0; q < 4; q++) d[n][q] = 0.f;

    // ---- GEMM1 hi-pass: Ahi*Bhi + Alo*Bhi ----
#pragma unroll 1
    for (int ks = 0; ks < 8; ks++) {
        u32 ah[4];
        LDMX4(ah[0], ah[1], ah[2], ah[3], sAhi_b + aoff + ks * 32);
#pragma unroll
        for (int j = 0; j < 8; j++) {
            u32 b0, b1, b2r, b3;
            LDMX4(b0, b1, b2r, b3, sBhi_b + boff + j * (16 * BROW) + ks * 32);
            MMA16816(d[2 * j],     ah[0], ah[1], ah[2], ah[3], b0, b1);
            MMA16816(d[2 * j + 1], ah[0], ah[1], ah[2], ah[3], b2r, b3);
            MMA16816(d[2 * j],     alo[ks][0], alo[ks][1], alo[ks][2], alo[ks][3], b0, b1);
            MMA16816(d[2 * j + 1], alo[ks][0], alo[ks][1], alo[ks][2], alo[ks][3], b2r, b3);
        }
    }
    CPWAIT0();
    __syncthreads();

    // ---- GEMM1 lo-pass: Ahi*Blo ----
#pragma unroll 1
    for (int ks = 0; ks < 8; ks++) {
        u32 ah[4];
        LDMX4(ah[0], ah[1], ah[2], ah[3], sAhi_b + aoff + ks * 32);
#pragma unroll
        for (int j = 0; j < 8; j++) {
            u32 b0, b1, b2r, b3;
            LDMX4(b0, b1, b2r, b3, sB2_b + boff + j * (16 * BROW) + ks * 32);
            MMA16816(d[2 * j],     ah[0], ah[1], ah[2], ah[3], b0, b1);
            MMA16816(d[2 * j + 1], ah[0], ah[1], ah[2], ah[3], b2r, b3);
        }
    }
    __syncthreads();   // all B/A reads done before restage/overwrite

    // ---- async stage CW1hi -> sBhi, CW1lo -> sB2 (overlaps readback) ----
    {
        const char* sh = (const char*)g_c1hi + ssrc;
        const char* sl = (const char*)g_c1lo + ssrc;
#pragma unroll
        for (int q = 0; q < 8; q++) {
            CPASYNC16(sdstBhi + q * 16, sh + q * 16);
            CPASYNC16(sdstB2  + q * 16, sl + q * 16);
        }
        CPCOMMIT();
    }

    // ---- readback GEMM1: +b2, silu, scatter m_i, A2hi->sAhi, A2lo->regs ----
    const int g = t5 >> 2, tg = t5 & 3;
    const int rowA = wid * 16 + g, rowB = rowA + 8;
    const int eA = rowA >> 2, tA = rowA & 3;
    const int eB = rowB >> 2, tB = rowB & 3;
    const bool okA = (e0 + eA) < E, okB = (e0 + eB) < E;
    float* mA = g_mi + ((size_t)s_rown[eA] * T + tA) * HD;
    float* mB = g_mi + ((size_t)s_rown[eB] * T + tB) * HD;

#pragma unroll
    for (int n = 0; n < 16; n++) {
        int c = 8 * n + 2 * tg;
        float v0 = silu_f(d[n][0] + s_bias[c]);
        float v1 = silu_f(d[n][1] + s_bias[c + 1]);
        float v2 = silu_f(d[n][2] + s_bias[c]);
        float v3 = silu_f(d[n][3] + s_bias[c + 1]);
        if (okA) REDV2(mA + c, v0, v1);
        if (okB) REDV2(mB + c, v2, v3);
        int ks = n >> 1, p = n & 1;
        u32 hh, ll;
        split2(v0, v1, hh, ll);
        *(u32*)(sAhi + rowA * BROW + c * 2) = hh;
        alo[ks][2 * p] = ll;
        split2(v2, v3, hh, ll);
        *(u32*)(sAhi + rowB * BROW + c * 2) = hh;
        alo[ks][2 * p + 1] = ll;
        d[n][0] = d[n][1] = d[n][2] = d[n][3] = 0.f;
    }
    CPWAIT0();
    __syncthreads();

    // ---- GEMM2 single pass: A2hi*Bhi + A2lo*Bhi + A2hi*Blo ----
#pragma unroll 1
    for (int ks = 0; ks < 8; ks++) {
        u32 ah[4];
        LDMX4(ah[0], ah[1], ah[2], ah[3], sAhi_b + aoff + ks * 32);
#pragma unroll
        for (int j = 0; j < 8; j++) {
            u32 bh0, bh1, bh2, bh3, bl0, bl1, bl2, bl3;
            LDMX4(bh0, bh1, bh2, bh3, sBhi_b + boff + j * (16 * BROW) + ks * 32);
            LDMX4(bl0, bl1, bl2, bl3, sB2_b  + boff + j * (16 * BROW) + ks * 32);
            MMA16816(d[2 * j],     ah[0], ah[1], ah[2], ah[3], bh0, bh1);
            MMA16816(d[2 * j + 1], ah[0], ah[1], ah[2], ah[3], bh2, bh3);
            MMA16816(d[2 * j],     alo[ks][0], alo[ks][1], alo[ks][2], alo[ks][3], bh0, bh1);
            MMA16816(d[2 * j + 1], alo[ks][0], alo[ks][1], alo[ks][2], alo[ks][3], bh2, bh3);
            MMA16816(d[2 * j],     ah[0], ah[1], ah[2], ah[3], bl0, bl1);
            MMA16816(d[2 * j + 1], ah[0], ah[1], ah[2], ah[3], bl2, bl3);
        }
    }

    // ---- readback GEMM2: silu, dot cw2, quad-reduce, coord epilogue ----
    {
        float pA = 0.f, pB = 0.f;
#pragma unroll
        for (int n = 0; n < 16; n++) {
            int c = 8 * n + 2 * tg;
            pA += silu_f(d[n][0] + s_bias[128 + c])     * s_bias[256 + c];
            pA += silu_f(d[n][1] + s_bias[128 + c + 1]) * s_bias[256 + c + 1];
            pB += silu_f(d[n][2] + s_bias[128 + c])     * s_bias[256 + c];
            pB += silu_f(d[n][3] + s_bias[128 + c + 1]) * s_bias[256 + c + 1];
        }
        pA += __shfl_xor_sync(0xffffffffu, pA, 1);
        pA += __shfl_xor_sync(0xffffffffu, pA, 2);
        pB += __shfl_xor_sync(0xffffffffu, pB, 1);
        pB += __shfl_xor_sync(0xffffffffu, pB, 2);
        if (tg == 0) {
            float cb2v = cb2[0];
#pragma unroll
            for (int half = 0; half < 2; half++) {
                int row = half ? rowB : rowA;
                float p = half ? pB : pA;
                int e = row >> 2, t = row & 3;
                if (e0 + e < E) {
                    float cval = (p + cb2v) *
                        __fdividef(1.0f, sqrtf(s_n2[row] + EPSF) + 1.0f);
                    int node = s_rown[e];
#pragma unroll
                    for (int dd = 0; dd < 3; dd++)
                        atomicAdd(&g_agg[((size_t)node * 3 + dd) * T + t],
                                  cval * s_xij[e][dd][t]);
                    if (t == 0) atomicAdd(&g_cnt[node], 1.0f);
                }
            }
        }
    }
}

// ---------------- node kernel ([N,T,HD] g_mi gather) ----------------
__global__ __launch_bounds__(256, 2) void node_kernel(
    const float* __restrict__ x, const float* __restrict__ h,
    const float* __restrict__ nw1, const float* __restrict__ nb1,
    const float* __restrict__ nw2, const float* __restrict__ nb2,
    float* __restrict__ out_x, float* __restrict__ out_h, int N)
{
    extern __shared__ float sm[];
    float* s_buf = sm;
    float* s_w   = sm + HD * STRIDE;

    const int tid = threadIdx.x, tx = tid & 15, ty = tid >> 4;
    const int n0 = blockIdx.x * NPB;

#pragma unroll
    for (int it = 0; it < 2; it++) {
        int idx = it * 256 + tid;
        if (idx < NPB * 12) {
            int n = n0 + idx / 12;
            if (n < N) {
                int rem = idx % 12, d = rem >> 2, t = rem & 3;
                float cv = fmaxf(g_cnt[n], 1.0f);
                int off = (n * 3 + d) * T + t;
                out_x[off] = x[off] + g_agg[off] * __fdividef(1.0f, cv);
            }
        }
    }

#pragma unroll
    for (int it = 0; it < 8; it++) {
        int idx = it * 256 + tid;
        int k = idx & 63, nl = idx >> 6;
        int node = n0 + nl; if (node >= N) node = N - 1;
        float4 v = *(const float4*)(h + ((size_t)node * HH + k) * T);
        *(float4*)(s_buf + k * STRIDE + nl * 4) = v;
    }
#pragma unroll
    for (int it = 0; it < 8; it++) {
        int idx = it * 256 + tid;
        int kq = idx & 15, t = (idx >> 4) & 3, nl = idx >> 6;
        int node = n0 + nl; if (node >= N) node = N - 1;
        float4 v = *(const float4*)(g_mi + ((size_t)node * T + t) * HD + kq * 4);
        s_buf[(HH + kq * 4 + 0) * STRIDE + nl * 4 + t] = v.x;
        s_buf[(HH + kq * 4 + 1) * STRIDE + nl * 4 + t] = v.y;
        s_buf[(HH + kq * 4 + 2) * STRIDE + nl * 4 + t] = v.z;
        s_buf[(HH + kq * 4 + 3) * STRIDE + nl * 4 + t] = v.w;
    }

    u64 acc[8][4];
    {
        float4 bA = *(const float4*)(nb1 + 4 * tx);
        float4 bB = *(const float4*)(nb1 + 64 + 4 * tx);
        u64 i0 = packab(bA.x, bA.y), i1 = packab(bA.z, bA.w);
        u64 i2 = packab(bB.x, bB.y), i3 = packab(bB.z, bB.w);
#pragma unroll
        for (int r = 0; r < 8; r++) {
            acc[r][0] = i0; acc[r][1] = i1; acc[r][2] = i2; acc[r][3] = i3;
        }
    }
    float4 pre[4];
#pragma unroll
    for (int i = 0; i < 4; i++) {
        int off = i * 1024 + tid * 4;
        pre[i] = *(const float4*)(nw1 + (off >> 7) * HD + (off & 127));
    }
#pragma unroll 1
    for (int kc = 0; kc < 4; kc++) {
        __syncthreads();
#pragma unroll
        for (int i = 0; i < 4; i++)
            *(float4*)(s_w + i * 1024 + tid * 4) = pre[i];
        __syncthreads();
        {
            int kbase = (kc + 1) * 32;
            if (kbase < 192) {
#pragma unroll
                for (int i = 0; i < 4; i++) {
                    int off = i * 1024 + tid * 4;
                    pre[i] = *(const float4*)(nw1 + (kbase + (off >> 7)) * HD + (off & 127));
                }
            }
        }
        const float* ap = s_buf + (kc * 32) * STRIDE + ty * 8;
#pragma unroll 8
        for (int kk = 0; kk < 32; kk++) {
            float4 a0 = *(const float4*)(ap);
            float4 a1 = *(const float4*)(ap + 4);
            ap += STRIDE;
            ulonglong2 bA = *(const ulonglong2*)(s_w + kk * HD + 4 * tx);
            ulonglong2 bB = *(const ulonglong2*)(s_w + kk * HD + 64 + 4 * tx);
            float av[8] = {a0.x, a0.y, a0.z, a0.w, a1.x, a1.y, a1.z, a1.w};
#pragma unroll
            for (int r = 0; r < 8; r++) {
                u64 ar = pack2(av[r]);
                FMA2(acc[r][0], ar, bA.x);
                FMA2(acc[r][1], ar, bA.y);
                FMA2(acc[r][2], ar, bB.x);
                FMA2(acc[r][3], ar, bB.y);
            }
        }
    }
    __syncthreads();

#pragma unroll
    for (int it = 0; it < 8; it++) {
        int idx = it * 256 + tid;
        int kq = idx & 15, t = (idx >> 4) & 3, nl = idx >> 6;
        int node = n0 + nl; if (node >= N) node = N - 1;
        float4 v = *(const float4*)(g_mi + ((size_t)node * T + t) * HD + 64 + kq * 4);
        s_buf[(kq * 4 + 0) * STRIDE + nl * 4 + t] = v.x;
        s_buf[(kq * 4 + 1) * STRIDE + nl * 4 + t] = v.y;
        s_buf[(kq * 4 + 2) * STRIDE + nl * 4 + t] = v.z;
        s_buf[(kq * 4 + 3) * STRIDE + nl * 4 + t] = v.w;
    }
#pragma unroll 1
    for (int kc = 0; kc < 2; kc++) {
        __syncthreads();
#pragma unroll
        for (int i = 0; i < 4; i++)
            *(float4*)(s_w + i * 1024 + tid * 4) = pre[i];
        __syncthreads();
        if (kc == 0) {
#pragma unroll
            for (int i = 0; i < 4; i++) {
                int off = i * 1024 + tid * 4;
                pre[i] = *(const float4*)(nw1 + (160 + (off >> 7)) * HD + (off & 127));
            }
        }
        const float* ap = s_buf + (kc * 32) * STRIDE + ty * 8;
#pragma unroll 8
        for (int kk = 0; kk < 32; kk++) {
            float4 a0 = *(const float4*)(ap);
            float4 a1 = *(const float4*)(ap + 4);
            ap += STRIDE;
            ulonglong2 bA = *(const ulonglong2*)(s_w + kk * HD + 4 * tx);
            ulonglong2 bB = *(const ulonglong2*)(s_w + kk * HD + 64 + 4 * tx);
            float av[8] = {a0.x, a0.y, a0.z, a0.w, a1.x, a1.y, a1.z, a1.w};
#pragma unroll
            for (int r = 0; r < 8; r++) {
                u64 ar = pack2(av[r]);
                FMA2(acc[r][0], ar, bA.x);
                FMA2(acc[r][1], ar, bA.y);
                FMA2(acc[r][2], ar, bB.x);
                FMA2(acc[r][3], ar, bB.y);
            }
        }
    }

    float o1[8][8];
#pragma unroll
    for (int r = 0; r < 8; r++)
#pragma unroll
        for (int cp = 0; cp < 4; cp++) {
            float lo, hi; unpack2(acc[r][cp], lo, hi);
            o1[r][2 * cp]     = silu_f(lo);
            o1[r][2 * cp + 1] = silu_f(hi);
        }
    __syncthreads();
#pragma unroll
    for (int c = 0; c < 8; c++) {
        int col = (c < 4) ? 4 * tx + c : 60 + 4 * tx + c;
        *(float4*)(s_buf + col * STRIDE + ty * 8) =
            make_float4(o1[0][c], o1[1][c], o1[2][c], o1[3][c]);
        *(float4*)(s_buf + col * STRIDE + ty * 8 + 4) =
            make_float4(o1[4][c], o1[5][c], o1[6][c], o1[7][c]);
    }

    u64 acc2[8][2];
    {
        float4 b = *(const float4*)(nb2 + 4 * tx);
        u64 i0 = packab(b.x, b.y), i1 = packab(b.z, b.w);
#pragma unroll
        for (int r = 0; r < 8; r++) { acc2[r][0] = i0; acc2[r][1] = i1; }
    }
    float4 pre2[2];
#pragma unroll
    for (int i = 0; i < 2; i++) {
        int off = i * 1024 + tid * 4;
        pre2[i] = *(const float4*)(nw2 + (off >> 6) * HH + (off & 63));
    }
#pragma unroll 1
    for (int kc = 0; kc < 4; kc++) {
        __syncthreads();
#pragma unroll
        for (int i = 0; i < 2; i++)
            *(float4*)(s_w + i * 1024 + tid * 4) = pre2[i];
        __syncthreads();
        if (kc < 3) {
#pragma unroll
            for (int i = 0; i < 2; i++) {
                int off = i * 1024 + tid * 4;
                pre2[i] = *(const float4*)(nw2 + ((kc + 1) * 32 + (off >> 6)) * HH + (off & 63));
            }
        }
        const float* ap = s_buf + (kc * 32) * STRIDE + ty * 8;
#pragma unroll 8
        for (int kk = 0; kk < 32; kk++) {
            float4 a0 = *(const float4*)(ap);
            float4 a1 = *(const float4*)(ap + 4);
            ap += STRIDE;
            ulonglong2 w01 = *(const ulonglong2*)(s_w + kk * HH + 4 * tx);
            float av[8] = {a0.x, a0.y, a0.z, a0.w, a1.x, a1.y, a1.z, a1.w};
#pragma unroll
            for (int r = 0; r < 8; r++) {
                u64 ar = pack2(av[r]);
                FMA2(acc2[r][0], ar, w01.x);
                FMA2(acc2[r][1], ar, w01.y);
            }
        }
    }
    float o2[8][4];
#pragma unroll
    for (int r = 0; r < 8; r++) {
        unpack2(acc2[r][0], o2[r][0], o2[r][1]);
        unpack2(acc2[r][1], o2[r][2], o2[r][3]);
    }
#pragma unroll
    for (int half = 0; half < 2; half++) {
        int n = n0 + 2 * ty + half;
        if (n < N) {
#pragma unroll
            for (int c = 0; c < 4; c++) {
                int col = 4 * tx + c;
                *(float4*)(out_h + ((size_t)n * HH + col) * T) =
                    make_float4(o2[half * 4 + 0][c], o2[half * 4 + 1][c],
                                o2[half * 4 + 2][c], o2[half * 4 + 3][c]);
            }
        }
    }
}

extern "C" void kernel_launch(void* const* d_in, const int* in_sizes, int n_in,
                              void* d_out, int out_size)
{
    const float* x   = (const float*)d_in[0];
    const float* h   = (const float*)d_in[1];
    const int*   ei  = (const int*)  d_in[2];
    const float* ea  = (const float*)d_in[3];
    const float* ew1 = (const float*)d_in[5];
    const float* eb1 = (const float*)d_in[6];
    const float* ew2 = (const float*)d_in[7];
    const float* eb2 = (const float*)d_in[8];
    const float* cw1 = (const float*)d_in[9];
    const float* cb1 = (const float*)d_in[10];
    const float* cw2 = (const float*)d_in[11];
    const float* cb2 = (const float*)d_in[12];
    const float* nw1 = (const float*)d_in[13];
    const float* nb1 = (const float*)d_in[14];
    const float* nw2 = (const float*)d_in[15];
    const float* nb2 = (const float*)d_in[16];

    int N = in_sizes[0] / (3 * T);
    int E = in_sizes[3] / (HE * T);

    float* out_x = (float*)d_out;
    float* out_h = out_x + (size_t)N * 3 * T;

    const int pre_smem  = (HH * STRIDE + 32 * HD) * sizeof(float);
    const int node_smem = (HD * STRIDE + 32 * HD) * sizeof(float);
    const int edge_smem = 105984;
    cudaFuncSetAttribute(pre_kernel,  cudaFuncAttributeMaxDynamicSharedMemorySize, pre_smem);
    cudaFuncSetAttribute(node_kernel, cudaFuncAttributeMaxDynamicSharedMemorySize, node_smem);
    cudaFuncSetAttribute(edge_kernel, cudaFuncAttributeMaxDynamicSharedMemorySize, edge_smem);

    zero_kernel<<<2048, 256>>>(N);
    wimg_kernel<<<(HD * HD) / 256, 256>>>(ew2, cw1);
    pre_kernel<<<(N + NPRE - 1) / NPRE, 256, pre_smem>>>(h, ew1, N);
    edge_kernel<<<(E + EPB - 1) / EPB, 256, edge_smem>>>(
        x, ei, ea, ew1, eb1, eb2, cb1, cw2, cb2, E);
    node_kernel<<<(N + NPB - 1) / NPB, 256, node_smem>>>(
        x, h, nw1, nb1, nw2, nb2, out_x, out_h, N);
}